// round 2
// baseline (speedup 1.0000x reference)
#include <cuda_runtime.h>

// Problem constants
#define Bc   4
#define Sc   2048
#define Ec   1024
#define Hc   16
#define HDc  64
#define Mrows (Bc * Sc)   // 8192

// Scratch (static device arrays: allocation-free per harness rules)
// Layout for q/k/v: [B, H, S, HD]; g_attn: [B, S, E]
__device__ float g_q[Mrows * Ec];
__device__ float g_k[Mrows * Ec];
__device__ float g_v[Mrows * Ec];
__device__ float g_attn[Mrows * Ec];

// ---------------------------------------------------------------------------
// GEMM: C[M,N] = A[M,K] @ W[N,K]^T + bias[N]
// BM=BN=64, BK=16, 256 threads, 4x4 per thread, SMEM tiles stored K-outer
// SCATTER=1: write to [B,H,S,HD] head layout instead of [M,N] row-major.
// ---------------------------------------------------------------------------
template <int SCATTER>
__global__ __launch_bounds__(256) void gemm_k(const float* __restrict__ A,
                                              const float* __restrict__ W,
                                              const float* __restrict__ bias,
                                              float* __restrict__ C) {
    const int K = Ec, N = Ec;
    __shared__ float As[16][64];   // [k][m]
    __shared__ float Ws[16][64];   // [k][n]

    const int tid = threadIdx.x;
    const int tx = tid & 15;       // 0..15 -> N
    const int ty = tid >> 4;       // 0..15 -> M
    const int r0 = blockIdx.x << 6;
    const int c0 = blockIdx.y << 6;

    const int lr = tid >> 2;          // 0..63: tile row (M or N)
    const int lc = (tid & 3) << 2;    // 0,4,8,12: k offset

    float acc[4][4];
#pragma unroll
    for (int i = 0; i < 4; i++)
#pragma unroll
        for (int j = 0; j < 4; j++) acc[i][j] = 0.f;

    const float* Ap = A + (size_t)(r0 + lr) * K + lc;
    const float* Wp = W + (size_t)(c0 + lr) * K + lc;

    for (int k0 = 0; k0 < K; k0 += 16) {
        float4 av = *(const float4*)(Ap + k0);
        float4 wv = *(const float4*)(Wp + k0);
        __syncthreads();
        As[lc + 0][lr] = av.x; As[lc + 1][lr] = av.y;
        As[lc + 2][lr] = av.z; As[lc + 3][lr] = av.w;
        Ws[lc + 0][lr] = wv.x; Ws[lc + 1][lr] = wv.y;
        Ws[lc + 2][lr] = wv.z; Ws[lc + 3][lr] = wv.w;
        __syncthreads();
#pragma unroll
        for (int kk = 0; kk < 16; kk++) {
            float4 a = *(const float4*)&As[kk][ty << 2];
            float4 w = *(const float4*)&Ws[kk][tx << 2];
            float a4[4] = {a.x, a.y, a.z, a.w};
            float w4[4] = {w.x, w.y, w.z, w.w};
#pragma unroll
            for (int i = 0; i < 4; i++)
#pragma unroll
                for (int j = 0; j < 4; j++) acc[i][j] += a4[i] * w4[j];
        }
    }

    // bias for this thread's 4 columns (hoisted)
    float b4[4];
#pragma unroll
    for (int j = 0; j < 4; j++) b4[j] = bias[c0 + (tx << 2) + j];

#pragma unroll
    for (int i = 0; i < 4; i++) {
        const int row = r0 + (ty << 2) + i;
#pragma unroll
        for (int j = 0; j < 4; j++) {
            const int col = c0 + (tx << 2) + j;
            const float v = acc[i][j] + b4[j];
            if (SCATTER) {
                const int b = row >> 11;          // row / Sc
                const int s = row & (Sc - 1);
                const int h = col >> 6;           // col / HDc
                const int d = col & (HDc - 1);
                C[(((size_t)(b * Hc + h)) * Sc + s) * HDc + d] = v;
            } else {
                C[(size_t)row * N + col] = v;
            }
        }
    }
}

// ---------------------------------------------------------------------------
// Flash-style causal attention. One block = 64 queries of one (b,h).
// SMEM: QsT[d][r], KsT[d][c], Vs[k][c], Ps[r][k]  (4 x 16KB = 64KB dynamic)
// 256 threads, 4x4 output tile per thread. Online softmax (m,l) per row.
// Writes output directly in [B,S,E] layout.
// ---------------------------------------------------------------------------
__global__ __launch_bounds__(256) void attn_k(const float* __restrict__ Q,
                                              const float* __restrict__ Kb,
                                              const float* __restrict__ Vb,
                                              float* __restrict__ O) {
    extern __shared__ float sm[];
    float* QsT = sm;            // [64][64]: [d][r]
    float* KsT = sm + 4096;     // [64][64]: [d][c]
    float* Vs  = sm + 8192;     // [64][64]: [k][c]
    float* Ps  = sm + 12288;    // [64][64]: [r][k]

    const int tid = threadIdx.x;
    const int tx = tid & 15;
    const int ty = tid >> 4;
    const int qt = blockIdx.x;
    const int bh = blockIdx.y;
    const int q0 = qt << 6;

    const float* qp = Q  + (size_t)bh * Sc * HDc;
    const float* kp = Kb + (size_t)bh * Sc * HDc;
    const float* vp = Vb + (size_t)bh * Sc * HDc;

    // Load Q tile transposed, pre-scaled by 1/sqrt(HD) = 0.125
#pragma unroll
    for (int i = 0; i < 4; i++) {
        const int lin = tid + (i << 8);
        const int r = lin >> 4;
        const int c4 = (lin & 15) << 2;
        float4 t = *(const float4*)&qp[(size_t)(q0 + r) * HDc + c4];
        QsT[(c4 + 0) * 64 + r] = t.x * 0.125f;
        QsT[(c4 + 1) * 64 + r] = t.y * 0.125f;
        QsT[(c4 + 2) * 64 + r] = t.z * 0.125f;
        QsT[(c4 + 3) * 64 + r] = t.w * 0.125f;
    }

    float m_i[4], l_i[4], acc[4][4];
#pragma unroll
    for (int i = 0; i < 4; i++) {
        m_i[i] = -1e30f;
        l_i[i] = 0.f;
#pragma unroll
        for (int j = 0; j < 4; j++) acc[i][j] = 0.f;
    }

    for (int kt = 0; kt <= qt; kt++) {
        const int k0 = kt << 6;
        // Stage K (transposed) and V tiles through registers
        float4 kreg[4], vreg[4];
#pragma unroll
        for (int i = 0; i < 4; i++) {
            const int lin = tid + (i << 8);
            const int r = lin >> 4;
            const int c4 = (lin & 15) << 2;
            kreg[i] = *(const float4*)&kp[(size_t)(k0 + r) * HDc + c4];
            vreg[i] = *(const float4*)&vp[(size_t)(k0 + r) * HDc + c4];
        }
        __syncthreads();   // everyone done reading Vs/Ps from previous tile
#pragma unroll
        for (int i = 0; i < 4; i++) {
            const int lin = tid + (i << 8);
            const int r = lin >> 4;
            const int c4 = (lin & 15) << 2;
            KsT[(c4 + 0) * 64 + r] = kreg[i].x;
            KsT[(c4 + 1) * 64 + r] = kreg[i].y;
            KsT[(c4 + 2) * 64 + r] = kreg[i].z;
            KsT[(c4 + 3) * 64 + r] = kreg[i].w;
            *(float4*)&Vs[r * 64 + c4] = vreg[i];
        }
        __syncthreads();

        // S = (Q/8) @ K^T for this 64x64 tile
        float s[4][4];
#pragma unroll
        for (int i = 0; i < 4; i++)
#pragma unroll
            for (int j = 0; j < 4; j++) s[i][j] = 0.f;

#pragma unroll 8
        for (int d = 0; d < 64; d++) {
            float4 a = *(const float4*)&QsT[d * 64 + (ty << 2)];
            float4 k4 = *(const float4*)&KsT[d * 64 + (tx << 2)];
            float av[4] = {a.x, a.y, a.z, a.w};
            float kv[4] = {k4.x, k4.y, k4.z, k4.w};
#pragma unroll
            for (int i = 0; i < 4; i++)
#pragma unroll
                for (int j = 0; j < 4; j++) s[i][j] += av[i] * kv[j];
        }

        // Causal mask on the diagonal tile
        if (kt == qt) {
#pragma unroll
            for (int i = 0; i < 4; i++)
#pragma unroll
                for (int j = 0; j < 4; j++)
                    if ((tx << 2) + j > (ty << 2) + i) s[i][j] = -1e30f;
        }

        // Online softmax update per row
#pragma unroll
        for (int i = 0; i < 4; i++) {
            float mx = fmaxf(fmaxf(s[i][0], s[i][1]), fmaxf(s[i][2], s[i][3]));
            mx = fmaxf(mx, __shfl_xor_sync(0xffffffffu, mx, 1));
            mx = fmaxf(mx, __shfl_xor_sync(0xffffffffu, mx, 2));
            mx = fmaxf(mx, __shfl_xor_sync(0xffffffffu, mx, 4));
            mx = fmaxf(mx, __shfl_xor_sync(0xffffffffu, mx, 8));
            const float mnew = fmaxf(m_i[i], mx);
            const float corr = __expf(m_i[i] - mnew);
            float rs = 0.f;
#pragma unroll
            for (int j = 0; j < 4; j++) {
                const float p = __expf(s[i][j] - mnew);
                s[i][j] = p;
                rs += p;
            }
            rs += __shfl_xor_sync(0xffffffffu, rs, 1);
            rs += __shfl_xor_sync(0xffffffffu, rs, 2);
            rs += __shfl_xor_sync(0xffffffffu, rs, 4);
            rs += __shfl_xor_sync(0xffffffffu, rs, 8);
            l_i[i] = l_i[i] * corr + rs;
            m_i[i] = mnew;
#pragma unroll
            for (int j = 0; j < 4; j++) acc[i][j] *= corr;
        }

        // Store P tile
#pragma unroll
        for (int i = 0; i < 4; i++)
#pragma unroll
            for (int j = 0; j < 4; j++)
                Ps[((ty << 2) + i) * 64 + (tx << 2) + j] = s[i][j];
        __syncthreads();

        // acc += P @ V
#pragma unroll 8
        for (int kk = 0; kk < 64; kk++) {
            float p4[4];
#pragma unroll
            for (int i = 0; i < 4; i++) p4[i] = Ps[((ty << 2) + i) * 64 + kk];
            float4 vv = *(const float4*)&Vs[kk * 64 + (tx << 2)];
            float v4[4] = {vv.x, vv.y, vv.z, vv.w};
#pragma unroll
            for (int i = 0; i < 4; i++)
#pragma unroll
                for (int j = 0; j < 4; j++) acc[i][j] += p4[i] * v4[j];
        }
    }

    // Epilogue: divide by l, write in [B, S, E] layout
    const int b = bh >> 4;
    const int h = bh & 15;
#pragma unroll
    for (int i = 0; i < 4; i++) {
        const float inv = 1.f / l_i[i];
        const int srow = q0 + (ty << 2) + i;
#pragma unroll
        for (int j = 0; j < 4; j++) {
            O[((size_t)(b * Sc + srow)) * Ec + h * HDc + (tx << 2) + j] =
                acc[i][j] * inv;
        }
    }
}

// ---------------------------------------------------------------------------
// Launch: QKV projections -> attention -> output projection
// Inputs: 0 values, 1 keys, 2 queries, 3 mask, 4 Wv, 5 bv, 6 Wk, 7 bk,
//         8 Wq, 9 bq, 10 Wo, 11 bo
// ---------------------------------------------------------------------------
extern "C" void kernel_launch(void* const* d_in, const int* in_sizes, int n_in,
                              void* d_out, int out_size) {
    const float* values  = (const float*)d_in[0];
    const float* keys    = (const float*)d_in[1];
    const float* queries = (const float*)d_in[2];
    const float* Wv = (const float*)d_in[4];
    const float* bv = (const float*)d_in[5];
    const float* Wk = (const float*)d_in[6];
    const float* bk = (const float*)d_in[7];
    const float* Wq = (const float*)d_in[8];
    const float* bq = (const float*)d_in[9];
    const float* Wo = (const float*)d_in[10];
    const float* bo = (const float*)d_in[11];
    float* out = (float*)d_out;

    float *qb, *kb, *vb, *ab;
    cudaGetSymbolAddress((void**)&qb, g_q);
    cudaGetSymbolAddress((void**)&kb, g_k);
    cudaGetSymbolAddress((void**)&vb, g_v);
    cudaGetSymbolAddress((void**)&ab, g_attn);

    cudaFuncSetAttribute(attn_k, cudaFuncAttributeMaxDynamicSharedMemorySize,
                         65536);

    dim3 gg(Mrows / 64, Ec / 64);   // (128, 16)
    gemm_k<1><<<gg, 256>>>(queries, Wq, bq, qb);
    gemm_k<1><<<gg, 256>>>(keys,    Wk, bk, kb);
    gemm_k<1><<<gg, 256>>>(values,  Wv, bv, vb);

    dim3 ga(Sc / 64, Bc * Hc);      // (32, 64)
    attn_k<<<ga, 256, 65536>>>(qb, kb, vb, ab);

    gemm_k<0><<<gg, 256>>>(ab, Wo, bo, out);
}

// round 3
// speedup vs baseline: 3.7303x; 3.7303x over previous
#include <cuda_runtime.h>
#include <cstdint>

#define Sc 2048
#define Ec 1024
#define Hc 16
#define HDc 64
#define Mrows 8192

// Scratch ([B,S,E] layout everywhere; heads addressed by column offset h*64)
__device__ float g_q[(size_t)Mrows * Ec];
__device__ float g_k[(size_t)Mrows * Ec];
__device__ float g_v[(size_t)Mrows * Ec];
__device__ float g_attn[(size_t)Mrows * Ec];

__device__ __forceinline__ uint32_t f2tf(float f) {
    uint32_t u;
    asm("cvt.rna.tf32.f32 %0, %1;" : "=r"(u) : "f"(f));
    return u;
}

__device__ __forceinline__ void mma8(float c[4], const uint32_t a[4],
                                     const uint32_t b[2]) {
    asm volatile(
        "mma.sync.aligned.m16n8k8.row.col.f32.tf32.tf32.f32 "
        "{%0,%1,%2,%3}, {%4,%5,%6,%7}, {%8,%9}, {%0,%1,%2,%3};\n"
        : "+f"(c[0]), "+f"(c[1]), "+f"(c[2]), "+f"(c[3])
        : "r"(a[0]), "r"(a[1]), "r"(a[2]), "r"(a[3]), "r"(b[0]), "r"(b[1]));
}

// ---------------------------------------------------------------------------
// GEMM: C[M,1024] = A[M,1024] @ W[1024,1024]^T + bias
// CTA tile 128x64, BK=32, 256 threads, warps 4(m) x 2(n), warp tile 32x32.
// tf32 mma m16n8k8, fp32 accumulate. SMEM stride 36 => conflict-free frags.
// ---------------------------------------------------------------------------
__global__ __launch_bounds__(256) void gemm_tc(const float* __restrict__ A,
                                               const float* __restrict__ W,
                                               const float* __restrict__ bias,
                                               float* __restrict__ C) {
    __shared__ uint32_t As[128][36];
    __shared__ uint32_t Ws[64][36];

    const int tid = threadIdx.x;
    const int lane = tid & 31, warp = tid >> 5;
    const int wm = warp >> 1, wn = warp & 1;
    const int gr = lane >> 2, gc = lane & 3;
    const int r0 = blockIdx.x << 7, c0 = blockIdx.y << 6;

    float acc[2][4][4];
#pragma unroll
    for (int mi = 0; mi < 2; mi++)
#pragma unroll
        for (int ni = 0; ni < 4; ni++)
#pragma unroll
            for (int j = 0; j < 4; j++) acc[mi][ni][j] = 0.f;

    const int arow = tid >> 3, acol = (tid & 7) << 2;
    const float* Ap = A + (size_t)(r0 + arow) * Ec + acol;
    const float* Wp = W + (size_t)(c0 + arow) * Ec + acol;

    float4 pa[4], pw[2];
#pragma unroll
    for (int i = 0; i < 4; i++)
        pa[i] = *(const float4*)(Ap + (size_t)(i << 5) * Ec);
#pragma unroll
    for (int i = 0; i < 2; i++)
        pw[i] = *(const float4*)(Wp + (size_t)(i << 5) * Ec);

    for (int k0 = 0; k0 < Ec; k0 += 32) {
        __syncthreads();
#pragma unroll
        for (int i = 0; i < 4; i++) {
            *(uint4*)&As[arow + (i << 5)][acol] =
                make_uint4(f2tf(pa[i].x), f2tf(pa[i].y), f2tf(pa[i].z),
                           f2tf(pa[i].w));
        }
#pragma unroll
        for (int i = 0; i < 2; i++) {
            *(uint4*)&Ws[arow + (i << 5)][acol] =
                make_uint4(f2tf(pw[i].x), f2tf(pw[i].y), f2tf(pw[i].z),
                           f2tf(pw[i].w));
        }
        __syncthreads();

        if (k0 + 32 < Ec) {
            Ap += 32;
            Wp += 32;
#pragma unroll
            for (int i = 0; i < 4; i++)
                pa[i] = *(const float4*)(Ap + (size_t)(i << 5) * Ec);
#pragma unroll
            for (int i = 0; i < 2; i++)
                pw[i] = *(const float4*)(Wp + (size_t)(i << 5) * Ec);
        }

#pragma unroll
        for (int ki = 0; ki < 4; ki++) {
            uint32_t af[2][4];
#pragma unroll
            for (int mi = 0; mi < 2; mi++) {
                const int rb = (wm << 5) + (mi << 4);
                af[mi][0] = As[rb + gr][(ki << 3) + gc];
                af[mi][1] = As[rb + gr + 8][(ki << 3) + gc];
                af[mi][2] = As[rb + gr][(ki << 3) + gc + 4];
                af[mi][3] = As[rb + gr + 8][(ki << 3) + gc + 4];
            }
#pragma unroll
            for (int ni = 0; ni < 4; ni++) {
                uint32_t bf[2];
                const int nb = (wn << 5) + (ni << 3) + gr;
                bf[0] = Ws[nb][(ki << 3) + gc];
                bf[1] = Ws[nb][(ki << 3) + gc + 4];
                mma8(acc[0][ni], af[0], bf);
                mma8(acc[1][ni], af[1], bf);
            }
        }
    }

    // Epilogue: bias + store (float2 per fragment row)
#pragma unroll
    for (int ni = 0; ni < 4; ni++) {
        const int col = c0 + (wn << 5) + (ni << 3) + (gc << 1);
        const float2 b2 = *(const float2*)&bias[col];
#pragma unroll
        for (int mi = 0; mi < 2; mi++) {
            const int row = r0 + (wm << 5) + (mi << 4) + gr;
            *(float2*)&C[(size_t)row * Ec + col] =
                make_float2(acc[mi][ni][0] + b2.x, acc[mi][ni][1] + b2.y);
            *(float2*)&C[(size_t)(row + 8) * Ec + col] =
                make_float2(acc[mi][ni][2] + b2.x, acc[mi][ni][3] + b2.y);
        }
    }
}

// ---------------------------------------------------------------------------
// Flash attention, tf32 tensor cores.
// CTA = 128 queries of one (b,h); 8 warps, each owns a 16-row strip (full
// row in-warp => softmax reduction is a quad shfl). K-tiles of 64.
// SMEM strides: Qs/Ks/Ps 68, Vs 72 -> all frag LDS patterns conflict-free.
// ---------------------------------------------------------------------------
__global__ __launch_bounds__(256) void attn_tc(const float* __restrict__ Q,
                                               const float* __restrict__ K,
                                               const float* __restrict__ V,
                                               float* __restrict__ O) {
    extern __shared__ uint32_t sm[];
    uint32_t* Qs = sm;                // [128][68]
    uint32_t* Ks = Qs + 128 * 68;     // [64][68]
    uint32_t* Vs = Ks + 64 * 68;      // [64][72]
    uint32_t* Ps = Vs + 64 * 72;      // [128][68]

    const int tid = threadIdx.x, lane = tid & 31, warp = tid >> 5;
    const int gr = lane >> 2, gc = lane & 3;
    const int qi = gridDim.x - 1 - blockIdx.x;  // heavy tiles launch first
    const int bh = blockIdx.y, b = bh >> 4, h = bh & 15;
    const int q0 = qi << 7;
    const int rb = warp << 4;

    const float* qb = Q + (size_t)b * Sc * Ec + h * HDc;
    const float* kb = K + (size_t)b * Sc * Ec + h * HDc;
    const float* vb = V + (size_t)b * Sc * Ec + h * HDc;

    // Load Q tile (pre-scaled by 1/sqrt(64)=0.125, tf32-rounded)
#pragma unroll
    for (int i = 0; i < 8; i++) {
        const int idx = tid + (i << 8);
        const int row = idx >> 4, c4 = (idx & 15) << 2;
        float4 t = *(const float4*)(qb + (size_t)(q0 + row) * Ec + c4);
        *(uint4*)&Qs[row * 68 + c4] =
            make_uint4(f2tf(t.x * 0.125f), f2tf(t.y * 0.125f),
                       f2tf(t.z * 0.125f), f2tf(t.w * 0.125f));
    }

    float m0 = -1e30f, m1 = -1e30f, l0 = 0.f, l1 = 0.f;
    float o[8][4];
#pragma unroll
    for (int ni = 0; ni < 8; ni++)
#pragma unroll
        for (int j = 0; j < 4; j++) o[ni][j] = 0.f;

    const int ktiles = (qi << 1) + 2;
    for (int kt = 0; kt < ktiles; kt++) {
        const int k0 = kt << 6;

        // Stage K/V tile through registers
        float4 kr[4], vr[4];
#pragma unroll
        for (int i = 0; i < 4; i++) {
            const int idx = tid + (i << 8);
            const int row = idx >> 4, c4 = (idx & 15) << 2;
            kr[i] = *(const float4*)(kb + (size_t)(k0 + row) * Ec + c4);
            vr[i] = *(const float4*)(vb + (size_t)(k0 + row) * Ec + c4);
        }
        __syncthreads();  // everyone done with previous Ks/Vs
#pragma unroll
        for (int i = 0; i < 4; i++) {
            const int idx = tid + (i << 8);
            const int row = idx >> 4, c4 = (idx & 15) << 2;
            *(uint4*)&Ks[row * 68 + c4] = make_uint4(
                f2tf(kr[i].x), f2tf(kr[i].y), f2tf(kr[i].z), f2tf(kr[i].w));
            *(uint4*)&Vs[row * 72 + c4] = make_uint4(
                f2tf(vr[i].x), f2tf(vr[i].y), f2tf(vr[i].z), f2tf(vr[i].w));
        }
        __syncthreads();

        // S = Q @ K^T (warp strip 16 x 64)
        float s[8][4];
#pragma unroll
        for (int ni = 0; ni < 8; ni++)
#pragma unroll
            for (int j = 0; j < 4; j++) s[ni][j] = 0.f;

#pragma unroll
        for (int ki = 0; ki < 8; ki++) {
            uint32_t af[4];
            af[0] = Qs[(rb + gr) * 68 + (ki << 3) + gc];
            af[1] = Qs[(rb + gr + 8) * 68 + (ki << 3) + gc];
            af[2] = Qs[(rb + gr) * 68 + (ki << 3) + gc + 4];
            af[3] = Qs[(rb + gr + 8) * 68 + (ki << 3) + gc + 4];
#pragma unroll
            for (int ni = 0; ni < 8; ni++) {
                uint32_t bf[2];
                const int nb = (ni << 3) + gr;
                bf[0] = Ks[nb * 68 + (ki << 3) + gc];
                bf[1] = Ks[nb * 68 + (ki << 3) + gc + 4];
                mma8(s[ni], af, bf);
            }
        }

        // Causal mask (only the two diagonal-overlapping tiles)
        if (k0 + 63 > q0) {
            const int row0 = q0 + rb + gr, row1 = row0 + 8;
#pragma unroll
            for (int ni = 0; ni < 8; ni++) {
                const int cg = k0 + (ni << 3) + (gc << 1);
                if (cg > row0) s[ni][0] = -1e30f;
                if (cg + 1 > row0) s[ni][1] = -1e30f;
                if (cg > row1) s[ni][2] = -1e30f;
                if (cg + 1 > row1) s[ni][3] = -1e30f;
            }
        }

        // Online softmax (rows r and r+8; quad reduction)
        float mx0 = -1e30f, mx1 = -1e30f;
#pragma unroll
        for (int ni = 0; ni < 8; ni++) {
            mx0 = fmaxf(mx0, fmaxf(s[ni][0], s[ni][1]));
            mx1 = fmaxf(mx1, fmaxf(s[ni][2], s[ni][3]));
        }
        mx0 = fmaxf(mx0, __shfl_xor_sync(0xffffffffu, mx0, 1));
        mx0 = fmaxf(mx0, __shfl_xor_sync(0xffffffffu, mx0, 2));
        mx1 = fmaxf(mx1, __shfl_xor_sync(0xffffffffu, mx1, 1));
        mx1 = fmaxf(mx1, __shfl_xor_sync(0xffffffffu, mx1, 2));

        const float mn0 = fmaxf(m0, mx0), mn1 = fmaxf(m1, mx1);
        const float cor0 = __expf(m0 - mn0), cor1 = __expf(m1 - mn1);
        float sum0 = 0.f, sum1 = 0.f;
#pragma unroll
        for (int ni = 0; ni < 8; ni++) {
            s[ni][0] = __expf(s[ni][0] - mn0);
            s[ni][1] = __expf(s[ni][1] - mn0);
            s[ni][2] = __expf(s[ni][2] - mn1);
            s[ni][3] = __expf(s[ni][3] - mn1);
            sum0 += s[ni][0] + s[ni][1];
            sum1 += s[ni][2] + s[ni][3];
        }
        sum0 += __shfl_xor_sync(0xffffffffu, sum0, 1);
        sum0 += __shfl_xor_sync(0xffffffffu, sum0, 2);
        sum1 += __shfl_xor_sync(0xffffffffu, sum1, 1);
        sum1 += __shfl_xor_sync(0xffffffffu, sum1, 2);

        l0 = l0 * cor0 + sum0;
        l1 = l1 * cor1 + sum1;
        m0 = mn0;
        m1 = mn1;
#pragma unroll
        for (int ni = 0; ni < 8; ni++) {
            o[ni][0] *= cor0;
            o[ni][1] *= cor0;
            o[ni][2] *= cor1;
            o[ni][3] *= cor1;
        }

        // Store P (warp-private rows) -> SMEM, tf32-rounded
#pragma unroll
        for (int ni = 0; ni < 8; ni++) {
            const int pc = (ni << 3) + (gc << 1);
            Ps[(rb + gr) * 68 + pc] = f2tf(s[ni][0]);
            Ps[(rb + gr) * 68 + pc + 1] = f2tf(s[ni][1]);
            Ps[(rb + gr + 8) * 68 + pc] = f2tf(s[ni][2]);
            Ps[(rb + gr + 8) * 68 + pc + 1] = f2tf(s[ni][3]);
        }
        __syncwarp();

        // O += P @ V
#pragma unroll
        for (int ki = 0; ki < 8; ki++) {
            uint32_t af[4];
            af[0] = Ps[(rb + gr) * 68 + (ki << 3) + gc];
            af[1] = Ps[(rb + gr + 8) * 68 + (ki << 3) + gc];
            af[2] = Ps[(rb + gr) * 68 + (ki << 3) + gc + 4];
            af[3] = Ps[(rb + gr + 8) * 68 + (ki << 3) + gc + 4];
#pragma unroll
            for (int ni = 0; ni < 8; ni++) {
                uint32_t bf[2];
                const int nb = (ni << 3) + gr;
                bf[0] = Vs[((ki << 3) + gc) * 72 + nb];
                bf[1] = Vs[((ki << 3) + gc + 4) * 72 + nb];
                mma8(o[ni], af, bf);
            }
        }
    }

    // Epilogue: normalize, write [B,S,E]
    const float i0 = 1.f / l0, i1 = 1.f / l1;
    float* ob = O + (size_t)b * Sc * Ec + h * HDc;
    const int row0 = q0 + rb + gr;
#pragma unroll
    for (int ni = 0; ni < 8; ni++) {
        const int d = (ni << 3) + (gc << 1);
        *(float2*)&ob[(size_t)row0 * Ec + d] =
            make_float2(o[ni][0] * i0, o[ni][1] * i0);
        *(float2*)&ob[(size_t)(row0 + 8) * Ec + d] =
            make_float2(o[ni][2] * i1, o[ni][3] * i1);
    }
}

// ---------------------------------------------------------------------------
// Inputs: 0 values, 1 keys, 2 queries, 3 mask, 4 Wv, 5 bv, 6 Wk, 7 bk,
//         8 Wq, 9 bq, 10 Wo, 11 bo
// ---------------------------------------------------------------------------
extern "C" void kernel_launch(void* const* d_in, const int* in_sizes, int n_in,
                              void* d_out, int out_size) {
    const float* values = (const float*)d_in[0];
    const float* keys = (const float*)d_in[1];
    const float* queries = (const float*)d_in[2];
    const float* Wv = (const float*)d_in[4];
    const float* bv = (const float*)d_in[5];
    const float* Wk = (const float*)d_in[6];
    const float* bk = (const float*)d_in[7];
    const float* Wq = (const float*)d_in[8];
    const float* bq = (const float*)d_in[9];
    const float* Wo = (const float*)d_in[10];
    const float* bo = (const float*)d_in[11];
    float* out = (float*)d_out;

    float *qb, *kb, *vb, *ab;
    cudaGetSymbolAddress((void**)&qb, g_q);
    cudaGetSymbolAddress((void**)&kb, g_k);
    cudaGetSymbolAddress((void**)&vb, g_v);
    cudaGetSymbolAddress((void**)&ab, g_attn);

    const int attn_smem = (128 * 68 + 64 * 68 + 64 * 72 + 128 * 68) * 4;
    cudaFuncSetAttribute(attn_tc, cudaFuncAttributeMaxDynamicSharedMemorySize,
                         attn_smem);

    dim3 gg(Mrows / 128, Ec / 64);  // (64, 16)
    gemm_tc<<<gg, 256>>>(queries, Wq, bq, qb);
    gemm_tc<<<gg, 256>>>(keys, Wk, bk, kb);
    gemm_tc<<<gg, 256>>>(values, Wv, bv, vb);

    dim3 ga(Sc / 128, 4 * Hc);  // (16, 64)
    attn_tc<<<ga, 256, attn_smem>>>(qb, kb, vb, ab);

    gemm_tc<<<gg, 256>>>(ab, Wo, bo, out);
}

// round 5
// speedup vs baseline: 4.0549x; 1.0870x over previous
#include <cuda_runtime.h>
#include <cstdint>

#define Sc 2048
#define Ec 1024
#define Hc 16
#define HDc 64
#define Mrows 8192

// Scratch ([B,S,E] layout everywhere; heads addressed by column offset h*64)
__device__ float g_q[(size_t)Mrows * Ec];
__device__ float g_k[(size_t)Mrows * Ec];
__device__ float g_v[(size_t)Mrows * Ec];
__device__ float g_attn[(size_t)Mrows * Ec];

__device__ __forceinline__ uint32_t f2tf(float f) {
    uint32_t u;
    asm("cvt.rna.tf32.f32 %0, %1;" : "=r"(u) : "f"(f));
    return u;
}

__device__ __forceinline__ void mma8(float c[4], const uint32_t a[4],
                                     const uint32_t b[2]) {
    asm volatile(
        "mma.sync.aligned.m16n8k8.row.col.f32.tf32.tf32.f32 "
        "{%0,%1,%2,%3}, {%4,%5,%6,%7}, {%8,%9}, {%0,%1,%2,%3};\n"
        : "+f"(c[0]), "+f"(c[1]), "+f"(c[2]), "+f"(c[3])
        : "r"(a[0]), "r"(a[1]), "r"(a[2]), "r"(a[3]), "r"(b[0]), "r"(b[1]));
}

// ---------------------------------------------------------------------------
// GEMM: C[M,1024] = A[M,1024] @ W[1024,1024]^T + bias
// CTA tile 128x128, BK=32, 256 threads, warps 2(m) x 4(n), warp tile 64x32.
// tf32 mma m16n8k8, fp32 accumulate, reg-prefetch pipeline.
// ---------------------------------------------------------------------------
__global__ __launch_bounds__(256) void gemm_tc(const float* __restrict__ A,
                                               const float* __restrict__ W,
                                               const float* __restrict__ bias,
                                               float* __restrict__ C) {
    __shared__ uint32_t As[128][36];
    __shared__ uint32_t Ws[128][36];

    const int tid = threadIdx.x;
    const int lane = tid & 31, warp = tid >> 5;
    const int wm = warp >> 2, wn = warp & 3;   // 2 x 4
    const int gr = lane >> 2, gc = lane & 3;
    const int r0 = blockIdx.x << 7, c0 = blockIdx.y << 7;

    float acc[4][4][4];
#pragma unroll
    for (int mi = 0; mi < 4; mi++)
#pragma unroll
        for (int ni = 0; ni < 4; ni++)
#pragma unroll
            for (int j = 0; j < 4; j++) acc[mi][ni][j] = 0.f;

    const int arow = tid >> 3, acol = (tid & 7) << 2;  // 32 rows/pass, 4 passes
    const float* Ap = A + (size_t)(r0 + arow) * Ec + acol;
    const float* Wp = W + (size_t)(c0 + arow) * Ec + acol;

    float4 pa[4], pw[4];
#pragma unroll
    for (int i = 0; i < 4; i++) {
        pa[i] = *(const float4*)(Ap + (size_t)(i << 5) * Ec);
        pw[i] = *(const float4*)(Wp + (size_t)(i << 5) * Ec);
    }

    for (int k0 = 0; k0 < Ec; k0 += 32) {
        __syncthreads();
#pragma unroll
        for (int i = 0; i < 4; i++) {
            *(uint4*)&As[arow + (i << 5)][acol] = make_uint4(
                f2tf(pa[i].x), f2tf(pa[i].y), f2tf(pa[i].z), f2tf(pa[i].w));
            *(uint4*)&Ws[arow + (i << 5)][acol] = make_uint4(
                f2tf(pw[i].x), f2tf(pw[i].y), f2tf(pw[i].z), f2tf(pw[i].w));
        }
        __syncthreads();

        if (k0 + 32 < Ec) {
            Ap += 32;
            Wp += 32;
#pragma unroll
            for (int i = 0; i < 4; i++) {
                pa[i] = *(const float4*)(Ap + (size_t)(i << 5) * Ec);
                pw[i] = *(const float4*)(Wp + (size_t)(i << 5) * Ec);
            }
        }

#pragma unroll
        for (int ki = 0; ki < 4; ki++) {
            uint32_t af[4][4];
#pragma unroll
            for (int mi = 0; mi < 4; mi++) {
                const int rb = (wm << 6) + (mi << 4);
                af[mi][0] = As[rb + gr][(ki << 3) + gc];
                af[mi][1] = As[rb + gr + 8][(ki << 3) + gc];
                af[mi][2] = As[rb + gr][(ki << 3) + gc + 4];
                af[mi][3] = As[rb + gr + 8][(ki << 3) + gc + 4];
            }
#pragma unroll
            for (int ni = 0; ni < 4; ni++) {
                uint32_t bf[2];
                const int nb = (wn << 5) + (ni << 3) + gr;
                bf[0] = Ws[nb][(ki << 3) + gc];
                bf[1] = Ws[nb][(ki << 3) + gc + 4];
#pragma unroll
                for (int mi = 0; mi < 4; mi++) mma8(acc[mi][ni], af[mi], bf);
            }
        }
    }

    // Epilogue: bias + store
#pragma unroll
    for (int ni = 0; ni < 4; ni++) {
        const int col = c0 + (wn << 5) + (ni << 3) + (gc << 1);
        const float2 b2 = *(const float2*)&bias[col];
#pragma unroll
        for (int mi = 0; mi < 4; mi++) {
            const int row = r0 + (wm << 6) + (mi << 4) + gr;
            *(float2*)&C[(size_t)row * Ec + col] =
                make_float2(acc[mi][ni][0] + b2.x, acc[mi][ni][1] + b2.y);
            *(float2*)&C[(size_t)(row + 8) * Ec + col] =
                make_float2(acc[mi][ni][2] + b2.x, acc[mi][ni][3] + b2.y);
        }
    }
}

// ---------------------------------------------------------------------------
// Flash attention, tf32 tensor cores, software-pipelined K/V staging.
// CTA = 128 queries of one (b,h); 8 warps, each owns a 16-row strip.
// K/V staging: 256 thr x float4 = 1024 floats/pass; 64x64 tile = 4 passes.
// ---------------------------------------------------------------------------
__global__ __launch_bounds__(256) void attn_tc(const float* __restrict__ Q,
                                               const float* __restrict__ K,
                                               const float* __restrict__ V,
                                               float* __restrict__ O) {
    extern __shared__ uint32_t sm[];
    uint32_t* Qs = sm;                // [128][68]
    uint32_t* Ks = Qs + 128 * 68;     // [64][68]
    uint32_t* Vs = Ks + 64 * 68;      // [64][72]
    uint32_t* Ps = Vs + 64 * 72;      // [128][68]

    const int tid = threadIdx.x, lane = tid & 31, warp = tid >> 5;
    const int gr = lane >> 2, gc = lane & 3;
    const int qi = gridDim.x - 1 - blockIdx.x;  // heavy tiles launch first
    const int bh = blockIdx.y, b = bh >> 4, h = bh & 15;
    const int q0 = qi << 7;
    const int rb = warp << 4;

    const float* qb = Q + (size_t)b * Sc * Ec + h * HDc;
    const float* kb = K + (size_t)b * Sc * Ec + h * HDc;
    const float* vb = V + (size_t)b * Sc * Ec + h * HDc;

    // Stage Q tile (pre-scaled by 1/sqrt(64)=0.125, tf32-rounded)
#pragma unroll
    for (int i = 0; i < 8; i++) {
        const int idx = tid + (i << 8);
        const int row = idx >> 4, c4 = (idx & 15) << 2;
        float4 t = *(const float4*)(qb + (size_t)(q0 + row) * Ec + c4);
        *(uint4*)&Qs[row * 68 + c4] =
            make_uint4(f2tf(t.x * 0.125f), f2tf(t.y * 0.125f),
                       f2tf(t.z * 0.125f), f2tf(t.w * 0.125f));
    }

    // Prefetch tile 0 of K/V into registers (4 passes of 16 rows each)
    const int srow = tid >> 4, sc4 = (tid & 15) << 2;
    float4 kr[4], vr[4];
#pragma unroll
    for (int i = 0; i < 4; i++) {
        const int row = srow + (i << 4);
        kr[i] = *(const float4*)(kb + (size_t)row * Ec + sc4);
        vr[i] = *(const float4*)(vb + (size_t)row * Ec + sc4);
    }

    float m0 = -1e30f, m1 = -1e30f, l0 = 0.f, l1 = 0.f;
    float o[8][4];
#pragma unroll
    for (int ni = 0; ni < 8; ni++)
#pragma unroll
        for (int j = 0; j < 4; j++) o[ni][j] = 0.f;

    const int ktiles = (qi << 1) + 2;
    for (int kt = 0; kt < ktiles; kt++) {
        __syncthreads();  // previous tile's Ks/Vs reads done (Q staged, kt==0)
#pragma unroll
        for (int i = 0; i < 4; i++) {
            const int row = srow + (i << 4);
            *(uint4*)&Ks[row * 68 + sc4] = make_uint4(
                f2tf(kr[i].x), f2tf(kr[i].y), f2tf(kr[i].z), f2tf(kr[i].w));
            *(uint4*)&Vs[row * 72 + sc4] = make_uint4(
                f2tf(vr[i].x), f2tf(vr[i].y), f2tf(vr[i].z), f2tf(vr[i].w));
        }
        __syncthreads();

        // Prefetch next tile (latency hides under compute below)
        if (kt + 1 < ktiles) {
            const int nk0 = (kt + 1) << 6;
#pragma unroll
            for (int i = 0; i < 4; i++) {
                const int row = nk0 + srow + (i << 4);
                kr[i] = *(const float4*)(kb + (size_t)row * Ec + sc4);
                vr[i] = *(const float4*)(vb + (size_t)row * Ec + sc4);
            }
        }

        // S = Q @ K^T (warp strip 16 x 64)
        float s[8][4];
#pragma unroll
        for (int ni = 0; ni < 8; ni++)
#pragma unroll
            for (int j = 0; j < 4; j++) s[ni][j] = 0.f;

#pragma unroll
        for (int ki = 0; ki < 8; ki++) {
            uint32_t af[4];
            af[0] = Qs[(rb + gr) * 68 + (ki << 3) + gc];
            af[1] = Qs[(rb + gr + 8) * 68 + (ki << 3) + gc];
            af[2] = Qs[(rb + gr) * 68 + (ki << 3) + gc + 4];
            af[3] = Qs[(rb + gr + 8) * 68 + (ki << 3) + gc + 4];
#pragma unroll
            for (int ni = 0; ni < 8; ni++) {
                uint32_t bf[2];
                const int nb = (ni << 3) + gr;
                bf[0] = Ks[nb * 68 + (ki << 3) + gc];
                bf[1] = Ks[nb * 68 + (ki << 3) + gc + 4];
                mma8(s[ni], af, bf);
            }
        }

        // Causal mask (only diagonal-overlapping tiles)
        const int k0 = kt << 6;
        if (k0 + 63 > q0) {
            const int row0 = q0 + rb + gr, row1 = row0 + 8;
#pragma unroll
            for (int ni = 0; ni < 8; ni++) {
                const int cg = k0 + (ni << 3) + (gc << 1);
                if (cg > row0) s[ni][0] = -1e30f;
                if (cg + 1 > row0) s[ni][1] = -1e30f;
                if (cg > row1) s[ni][2] = -1e30f;
                if (cg + 1 > row1) s[ni][3] = -1e30f;
            }
        }

        // Online softmax (rows r and r+8; quad reduction)
        float mx0 = -1e30f, mx1 = -1e30f;
#pragma unroll
        for (int ni = 0; ni < 8; ni++) {
            mx0 = fmaxf(mx0, fmaxf(s[ni][0], s[ni][1]));
            mx1 = fmaxf(mx1, fmaxf(s[ni][2], s[ni][3]));
        }
        mx0 = fmaxf(mx0, __shfl_xor_sync(0xffffffffu, mx0, 1));
        mx0 = fmaxf(mx0, __shfl_xor_sync(0xffffffffu, mx0, 2));
        mx1 = fmaxf(mx1, __shfl_xor_sync(0xffffffffu, mx1, 1));
        mx1 = fmaxf(mx1, __shfl_xor_sync(0xffffffffu, mx1, 2));

        const float mn0 = fmaxf(m0, mx0), mn1 = fmaxf(m1, mx1);
        const float cor0 = __expf(m0 - mn0), cor1 = __expf(m1 - mn1);
        float sum0 = 0.f, sum1 = 0.f;
#pragma unroll
        for (int ni = 0; ni < 8; ni++) {
            s[ni][0] = __expf(s[ni][0] - mn0);
            s[ni][1] = __expf(s[ni][1] - mn0);
            s[ni][2] = __expf(s[ni][2] - mn1);
            s[ni][3] = __expf(s[ni][3] - mn1);
            sum0 += s[ni][0] + s[ni][1];
            sum1 += s[ni][2] + s[ni][3];
        }
        sum0 += __shfl_xor_sync(0xffffffffu, sum0, 1);
        sum0 += __shfl_xor_sync(0xffffffffu, sum0, 2);
        sum1 += __shfl_xor_sync(0xffffffffu, sum1, 1);
        sum1 += __shfl_xor_sync(0xffffffffu, sum1, 2);

        l0 = l0 * cor0 + sum0;
        l1 = l1 * cor1 + sum1;
        m0 = mn0;
        m1 = mn1;
#pragma unroll
        for (int ni = 0; ni < 8; ni++) {
            o[ni][0] *= cor0;
            o[ni][1] *= cor0;
            o[ni][2] *= cor1;
            o[ni][3] *= cor1;
        }

        // Store P (warp-private rows) -> SMEM, tf32-rounded
#pragma unroll
        for (int ni = 0; ni < 8; ni++) {
            const int pc = (ni << 3) + (gc << 1);
            Ps[(rb + gr) * 68 + pc] = f2tf(s[ni][0]);
            Ps[(rb + gr) * 68 + pc + 1] = f2tf(s[ni][1]);
            Ps[(rb + gr + 8) * 68 + pc] = f2tf(s[ni][2]);
            Ps[(rb + gr + 8) * 68 + pc + 1] = f2tf(s[ni][3]);
        }
        __syncwarp();

        // O += P @ V
#pragma unroll
        for (int ki = 0; ki < 8; ki++) {
            uint32_t af[4];
            af[0] = Ps[(rb + gr) * 68 + (ki << 3) + gc];
            af[1] = Ps[(rb + gr + 8) * 68 + (ki << 3) + gc];
            af[2] = Ps[(rb + gr) * 68 + (ki << 3) + gc + 4];
            af[3] = Ps[(rb + gr + 8) * 68 + (ki << 3) + gc + 4];
#pragma unroll
            for (int ni = 0; ni < 8; ni++) {
                uint32_t bf[2];
                const int nb = (ni << 3) + gr;
                bf[0] = Vs[((ki << 3) + gc) * 72 + nb];
                bf[1] = Vs[((ki << 3) + gc + 4) * 72 + nb];
                mma8(o[ni], af, bf);
            }
        }
    }

    // Epilogue: normalize, write [B,S,E]
    const float i0 = 1.f / l0, i1 = 1.f / l1;
    float* ob = O + (size_t)b * Sc * Ec + h * HDc;
    const int row0 = q0 + rb + gr;
#pragma unroll
    for (int ni = 0; ni < 8; ni++) {
        const int d = (ni << 3) + (gc << 1);
        *(float2*)&ob[(size_t)row0 * Ec + d] =
            make_float2(o[ni][0] * i0, o[ni][1] * i0);
        *(float2*)&ob[(size_t)(row0 + 8) * Ec + d] =
            make_float2(o[ni][2] * i1, o[ni][3] * i1);
    }
}

// ---------------------------------------------------------------------------
// Inputs: 0 values, 1 keys, 2 queries, 3 mask, 4 Wv, 5 bv, 6 Wk, 7 bk,
//         8 Wq, 9 bq, 10 Wo, 11 bo
// ---------------------------------------------------------------------------
extern "C" void kernel_launch(void* const* d_in, const int* in_sizes, int n_in,
                              void* d_out, int out_size) {
    const float* values = (const float*)d_in[0];
    const float* keys = (const float*)d_in[1];
    const float* queries = (const float*)d_in[2];
    const float* Wv = (const float*)d_in[4];
    const float* bv = (const float*)d_in[5];
    const float* Wk = (const float*)d_in[6];
    const float* bk = (const float*)d_in[7];
    const float* Wq = (const float*)d_in[8];
    const float* bq = (const float*)d_in[9];
    const float* Wo = (const float*)d_in[10];
    const float* bo = (const float*)d_in[11];
    float* out = (float*)d_out;

    float *qb, *kb, *vb, *ab;
    cudaGetSymbolAddress((void**)&qb, g_q);
    cudaGetSymbolAddress((void**)&kb, g_k);
    cudaGetSymbolAddress((void**)&vb, g_v);
    cudaGetSymbolAddress((void**)&ab, g_attn);

    const int attn_smem = (128 * 68 + 64 * 68 + 64 * 72 + 128 * 68) * 4;
    cudaFuncSetAttribute(attn_tc, cudaFuncAttributeMaxDynamicSharedMemorySize,
                         attn_smem);

    dim3 gg(Mrows / 128, Ec / 128);  // (64, 8)
    gemm_tc<<<gg, 256>>>(queries, Wq, bq, qb);
    gemm_tc<<<gg, 256>>>(keys, Wk, bk, kb);
    gemm_tc<<<gg, 256>>>(values, Wv, bv, vb);

    dim3 ga(Sc / 128, 4 * Hc);  // (16, 64)
    attn_tc<<<ga, 256, attn_smem>>>(qb, kb, vb, ab);

    gemm_tc<<<gg, 256>>>(ab, Wo, bo, out);
}

// round 7
// speedup vs baseline: 4.2494x; 1.0480x over previous
#include <cuda_runtime.h>
#include <cstdint>

#define Sc 2048
#define Ec 1024
#define Hc 16
#define HDc 64
#define Mrows 8192

// Scratch. q/k: [bh][s][d] tf32-bits; v: [bh][d][s] tf32-bits; attn: [b][s][e] tf32-bits
__device__ float g_q[(size_t)Mrows * Ec];
__device__ float g_k[(size_t)Mrows * Ec];
__device__ float g_v[(size_t)Mrows * Ec];
__device__ float g_attn[(size_t)Mrows * Ec];
// tf32 pre-converted weights + inputs
__device__ float g_wq[(size_t)Ec * Ec];
__device__ float g_wk[(size_t)Ec * Ec];
__device__ float g_wv[(size_t)Ec * Ec];
__device__ float g_wo[(size_t)Ec * Ec];
__device__ float g_qin[(size_t)Mrows * Ec];
__device__ float g_kin[(size_t)Mrows * Ec];
__device__ float g_vin[(size_t)Mrows * Ec];

__device__ __forceinline__ uint32_t f2tf(float f) {
    uint32_t u;
    asm("cvt.rna.tf32.f32 %0, %1;" : "=r"(u) : "f"(f));
    return u;
}

__device__ __forceinline__ void mma8(float c[4], const uint32_t a[4],
                                     const uint32_t b[2]) {
    asm volatile(
        "mma.sync.aligned.m16n8k8.row.col.f32.tf32.tf32.f32 "
        "{%0,%1,%2,%3}, {%4,%5,%6,%7}, {%8,%9}, {%0,%1,%2,%3};\n"
        : "+f"(c[0]), "+f"(c[1]), "+f"(c[2]), "+f"(c[3])
        : "r"(a[0]), "r"(a[1]), "r"(a[2]), "r"(a[3]), "r"(b[0]), "r"(b[1]));
}

__device__ __forceinline__ void ldsm4(uint32_t r[4], uint32_t a) {
    asm volatile(
        "ldmatrix.sync.aligned.m8n8.x4.shared.b16 {%0,%1,%2,%3}, [%4];"
        : "=r"(r[0]), "=r"(r[1]), "=r"(r[2]), "=r"(r[3])
        : "r"(a));
}

__device__ __forceinline__ void cp16(uint32_t s, const float* g) {
    asm volatile("cp.async.cg.shared.global [%0], [%1], 16;" ::"r"(s), "l"(g)
                 : "memory");
}
#define CP_COMMIT asm volatile("cp.async.commit_group;" ::: "memory")
#define CP_WAIT(n) asm volatile("cp.async.wait_group %0;" ::"n"(n) : "memory")
#define STS64(a, u0, u1) \
    asm volatile("st.shared.v2.b32 [%0], {%1,%2};" ::"r"(a), "r"(u0), "r"(u1))

// ---------------------------------------------------------------------------
// tf32 pre-convert (elementwise, float4)
// ---------------------------------------------------------------------------
__global__ void conv_tf(const float4* __restrict__ src, uint4* __restrict__ dst,
                        int n4) {
    int i = blockIdx.x * blockDim.x + threadIdx.x;
    const int stride = gridDim.x * blockDim.x;
    for (; i < n4; i += stride) {
        float4 v = src[i];
        dst[i] = make_uint4(f2tf(v.x), f2tf(v.y), f2tf(v.z), f2tf(v.w));
    }
}

// ---------------------------------------------------------------------------
// GEMM: C[M,1024] = A @ W^T + bias. Inputs already tf32-bits.
// CTA 128x128, BK=32, 2-stage cp.async pipeline, ldmatrix fragments.
// EPI: 0 plain fp32 out; 1 Q (x0.125, tf32, [bh][s][d]); 2 K (tf32, [bh][s][d]);
//      3 V (tf32, transposed [bh][d][s])
// SMEM per stage: As 128x36 + Ws 128x36 words = 36864 B; 2 stages = 73728 B
// ---------------------------------------------------------------------------
template <int EPI>
__global__ void __launch_bounds__(256, 2)
    gemm_tc(const float* __restrict__ A, const float* __restrict__ W,
            const float* __restrict__ bias, float* __restrict__ C) {
    extern __shared__ uint32_t gsm[];
    const uint32_t smb = (uint32_t)__cvta_generic_to_shared(gsm);

    const int tid = threadIdx.x, lane = tid & 31, warp = tid >> 5;
    const int wm = warp >> 2, wn = warp & 3;  // 2(m) x 4(n)
    const int gr = lane >> 2, gc = lane & 3;
    const int r0 = blockIdx.x << 7, c0 = blockIdx.y << 7;

    const int lm15 = lane & 15;
    const int colA = ((lane >> 4) & 1) << 2;  // A frag k-half
    const int l7 = lane & 7;
    const int l16 = (lane >> 4) & 1;
    const int colB = ((lane >> 3) & 1) << 2;  // B frag k-half

    // ldmatrix lane byte-offsets (within stage)
    const uint32_t a_lane = (((wm << 6) + lm15) * 36 + colA) << 2;
    const uint32_t b_lane = (((wn << 5) + (l16 << 3) + l7) * 36 + colB) << 2;

    // cp.async staging coords: 32 rows/pass, 8 lanes x 16B per row
    const int srow = tid >> 3, scol = (tid & 7) << 2;
    const float* Ap = A + (size_t)(r0 + srow) * Ec + scol;
    const float* Wp = W + (size_t)(c0 + srow) * Ec + scol;
    const uint32_t dA = smb + ((srow * 36 + scol) << 2);
    const uint32_t dW = dA + 18432;

    float acc[4][4][4];
#pragma unroll
    for (int mi = 0; mi < 4; mi++)
#pragma unroll
        for (int ni = 0; ni < 4; ni++)
#pragma unroll
            for (int j = 0; j < 4; j++) acc[mi][ni][j] = 0.f;

    // prologue: stage chunk 0
#pragma unroll
    for (int p = 0; p < 4; p++) {
        cp16(dA + p * (32 * 36 * 4), Ap + (size_t)(p << 5) * Ec);
        cp16(dW + p * (32 * 36 * 4), Wp + (size_t)(p << 5) * Ec);
    }
    CP_COMMIT;

    for (int c = 0; c < 32; c++) {
        __syncthreads();
        if (c + 1 < 32) {
            const uint32_t st = ((c + 1) & 1) * 36864;
            const float* Ap2 = Ap + (c + 1) * 32;
            const float* Wp2 = Wp + (c + 1) * 32;
#pragma unroll
            for (int p = 0; p < 4; p++) {
                cp16(dA + st + p * (32 * 36 * 4), Ap2 + (size_t)(p << 5) * Ec);
                cp16(dW + st + p * (32 * 36 * 4), Wp2 + (size_t)(p << 5) * Ec);
            }
            CP_COMMIT;
            CP_WAIT(1);
        } else {
            CP_WAIT(0);
        }
        __syncthreads();

        const uint32_t asb = smb + (c & 1) * 36864;
        const uint32_t wsb = asb + 18432;
#pragma unroll
        for (int ki = 0; ki < 4; ki++) {
            uint32_t af[4][4];
#pragma unroll
            for (int mi = 0; mi < 4; mi++)
                ldsm4(af[mi], asb + a_lane + mi * 2304 + ki * 32);
#pragma unroll
            for (int t = 0; t < 2; t++) {
                uint32_t bq[4];
                ldsm4(bq, wsb + b_lane + t * 2304 + ki * 32);
#pragma unroll
                for (int mi = 0; mi < 4; mi++) {
                    mma8(acc[mi][2 * t], af[mi], bq);
                    mma8(acc[mi][2 * t + 1], af[mi], bq + 2);
                }
            }
        }
    }

    // Epilogue
#pragma unroll
    for (int ni = 0; ni < 4; ni++) {
        const int col = c0 + (wn << 5) + (ni << 3) + (gc << 1);
        const float2 b2 = *(const float2*)&bias[col];
#pragma unroll
        for (int mi = 0; mi < 4; mi++) {
            const int row = r0 + (wm << 6) + (mi << 4) + gr;
            float v00 = acc[mi][ni][0] + b2.x, v01 = acc[mi][ni][1] + b2.y;
            float v10 = acc[mi][ni][2] + b2.x, v11 = acc[mi][ni][3] + b2.y;
            if (EPI == 0) {
                *(float2*)&C[(size_t)row * Ec + col] = make_float2(v00, v01);
                *(float2*)&C[(size_t)(row + 8) * Ec + col] =
                    make_float2(v10, v11);
            } else {
                if (EPI == 1) {
                    v00 *= 0.125f; v01 *= 0.125f; v10 *= 0.125f; v11 *= 0.125f;
                }
                const uint32_t u00 = f2tf(v00), u01 = f2tf(v01);
                const uint32_t u10 = f2tf(v10), u11 = f2tf(v11);
                const int b = row >> 11, s = row & (Sc - 1);
                const int h = col >> 6, d = col & (HDc - 1);
                const int bh = (b << 4) + h;
                if (EPI == 3) {
                    // [bh][d][s]
                    float* base0 = C + (((size_t)(bh << 6) + d) << 11) + s;
                    float* base1 = base0 + Sc;  // d+1
                    base0[0] = __uint_as_float(u00);
                    base0[8] = __uint_as_float(u10);
                    base1[0] = __uint_as_float(u01);
                    base1[8] = __uint_as_float(u11);
                } else {
                    // [bh][s][d]
                    float* base = C + ((size_t)bh << 17) + (s << 6) + d;
                    *(float2*)base = make_float2(__uint_as_float(u00),
                                                 __uint_as_float(u01));
                    *(float2*)(base + (8 << 6)) = make_float2(
                        __uint_as_float(u10), __uint_as_float(u11));
                }
            }
        }
    }
}

// ---------------------------------------------------------------------------
// Flash attention, tf32, ldmatrix + cp.async double-buffered K/V.
// CTA = 128 queries of one (b,h); 8 warps x 16-row strips; K-tile 64.
// Q/K/V already tf32-bits (Q pre-scaled). V in [bh][d][s].
// SMEM bytes: KV stage0 [0,34816) (K 17408 + V 17408), stage1 [34816,69632),
//             Ps/Qstage [69632,104448). Strides 68 words.
// Q is staged through the Ps region (disjoint from in-flight tile-0 cp.async),
// fragments pulled to registers, then Ps is reused for P tiles.
// ---------------------------------------------------------------------------
__global__ void __launch_bounds__(256, 2)
    attn_tc(const float* __restrict__ Q, const float* __restrict__ K,
            const float* __restrict__ V, float* __restrict__ O) {
    extern __shared__ uint32_t asm_sm[];
    const uint32_t smb = (uint32_t)__cvta_generic_to_shared(asm_sm);
    const uint32_t PsB = smb + 69632;

    const int tid = threadIdx.x, lane = tid & 31, warp = tid >> 5;
    const int gr = lane >> 2, gc = lane & 3;
    const int qi = gridDim.x - 1 - blockIdx.x;  // heavy tiles first
    const int bh = blockIdx.y;
    const int q0 = qi << 7;
    const int rb = warp << 4;

    const int lm15 = lane & 15;
    const int colA = ((lane >> 4) & 1) << 2;
    const int l7 = lane & 7;
    const int l16 = (lane >> 4) & 1;
    const int colB = ((lane >> 3) & 1) << 2;

    const uint32_t p_lane = (((rb + lm15) * 68 + colA) << 2);         // Q/P frags
    const uint32_t kb_lane = ((((l16 << 3) + l7) * 68 + colB) << 2);  // K/V frags

    const float* qb = Q + ((size_t)bh << 17);
    const float* kb = K + ((size_t)bh << 17);
    const float* vb = V + ((size_t)bh << 17);

    // cp.async staging coords: 16 rows/pass x 16 lanes x 16B
    const int srow = tid >> 4, sc4 = (tid & 15) << 2;
    const uint32_t dKV = smb + (((srow * 68) + sc4) << 2);

    // prologue: stage 0 K/V (tile 0) -- lands in [0, 34816), not touched
    // until after CP_WAIT in the first loop iteration.
#pragma unroll
    for (int p = 0; p < 4; p++) {
        const int r = srow + (p << 4);
        cp16(dKV + p * (16 * 68 * 4), kb + (size_t)r * HDc + sc4);
        cp16(dKV + 17408 + p * (16 * 68 * 4), vb + ((size_t)r << 11) + sc4);
    }
    CP_COMMIT;

    // stage Q through the Ps region (disjoint from cp.async targets)
#pragma unroll
    for (int p = 0; p < 8; p++) {
        const int idx = tid + (p << 8);
        const int row = idx >> 4, c4 = (idx & 15) << 2;
        uint4 t = *(const uint4*)(qb + (size_t)(q0 + row) * HDc + c4);
        *(uint4*)((char*)asm_sm + 69632 + ((row * 68 + c4) << 2)) = t;
    }
    __syncthreads();
    uint32_t qf[8][4];
#pragma unroll
    for (int ki = 0; ki < 8; ki++) ldsm4(qf[ki], PsB + p_lane + ki * 32);
    __syncthreads();  // all Q-frag reads done before Ps is reused for P

    float m0 = -1e30f, m1 = -1e30f, l0 = 0.f, l1 = 0.f;
    float o[8][4];
#pragma unroll
    for (int ni = 0; ni < 8; ni++)
#pragma unroll
        for (int j = 0; j < 4; j++) o[ni][j] = 0.f;

    const int ktiles = (qi << 1) + 2;
    for (int kt = 0; kt < ktiles; kt++) {
        __syncthreads();
        if (kt + 1 < ktiles) {
            const int nk0 = (kt + 1) << 6;
            const uint32_t st = ((kt + 1) & 1) * 34816;
#pragma unroll
            for (int p = 0; p < 4; p++) {
                const int r = srow + (p << 4);
                cp16(dKV + st + p * (16 * 68 * 4),
                     kb + (size_t)(nk0 + r) * HDc + sc4);
                cp16(dKV + st + 17408 + p * (16 * 68 * 4),
                     vb + ((size_t)r << 11) + nk0 + sc4);
            }
            CP_COMMIT;
            CP_WAIT(1);
        } else {
            CP_WAIT(0);
        }
        __syncthreads();

        const uint32_t ksb = smb + (kt & 1) * 34816;
        const uint32_t vsb = ksb + 17408;

        // S = Q @ K^T
        float s[8][4];
#pragma unroll
        for (int ni = 0; ni < 8; ni++)
#pragma unroll
            for (int j = 0; j < 4; j++) s[ni][j] = 0.f;
#pragma unroll
        for (int ki = 0; ki < 8; ki++) {
#pragma unroll
            for (int t = 0; t < 4; t++) {
                uint32_t bq[4];
                ldsm4(bq, ksb + kb_lane + t * 4352 + ki * 32);
                mma8(s[2 * t], qf[ki], bq);
                mma8(s[2 * t + 1], qf[ki], bq + 2);
            }
        }

        // causal mask on diagonal-overlapping tiles
        const int k0 = kt << 6;
        if (k0 + 63 > q0) {
            const int row0 = q0 + rb + gr, row1 = row0 + 8;
#pragma unroll
            for (int ni = 0; ni < 8; ni++) {
                const int cg = k0 + (ni << 3) + (gc << 1);
                if (cg > row0) s[ni][0] = -1e30f;
                if (cg + 1 > row0) s[ni][1] = -1e30f;
                if (cg > row1) s[ni][2] = -1e30f;
                if (cg + 1 > row1) s[ni][3] = -1e30f;
            }
        }

        // online softmax
        float mx0 = -1e30f, mx1 = -1e30f;
#pragma unroll
        for (int ni = 0; ni < 8; ni++) {
            mx0 = fmaxf(mx0, fmaxf(s[ni][0], s[ni][1]));
            mx1 = fmaxf(mx1, fmaxf(s[ni][2], s[ni][3]));
        }
        mx0 = fmaxf(mx0, __shfl_xor_sync(0xffffffffu, mx0, 1));
        mx0 = fmaxf(mx0, __shfl_xor_sync(0xffffffffu, mx0, 2));
        mx1 = fmaxf(mx1, __shfl_xor_sync(0xffffffffu, mx1, 1));
        mx1 = fmaxf(mx1, __shfl_xor_sync(0xffffffffu, mx1, 2));

        const float mn0 = fmaxf(m0, mx0), mn1 = fmaxf(m1, mx1);
        const float cor0 = __expf(m0 - mn0), cor1 = __expf(m1 - mn1);
        float sum0 = 0.f, sum1 = 0.f;
#pragma unroll
        for (int ni = 0; ni < 8; ni++) {
            s[ni][0] = __expf(s[ni][0] - mn0);
            s[ni][1] = __expf(s[ni][1] - mn0);
            s[ni][2] = __expf(s[ni][2] - mn1);
            s[ni][3] = __expf(s[ni][3] - mn1);
            sum0 += s[ni][0] + s[ni][1];
            sum1 += s[ni][2] + s[ni][3];
        }
        sum0 += __shfl_xor_sync(0xffffffffu, sum0, 1);
        sum0 += __shfl_xor_sync(0xffffffffu, sum0, 2);
        sum1 += __shfl_xor_sync(0xffffffffu, sum1, 1);
        sum1 += __shfl_xor_sync(0xffffffffu, sum1, 2);

        l0 = l0 * cor0 + sum0;
        l1 = l1 * cor1 + sum1;
        m0 = mn0;
        m1 = mn1;
#pragma unroll
        for (int ni = 0; ni < 8; ni++) {
            o[ni][0] *= cor0;
            o[ni][1] *= cor0;
            o[ni][2] *= cor1;
            o[ni][3] *= cor1;
        }

        // P -> Ps (tf32); rows are warp-private, __syncwarp suffices
#pragma unroll
        for (int ni = 0; ni < 8; ni++) {
            const uint32_t a0 =
                PsB + ((((rb + gr) * 68) + (ni << 3) + (gc << 1)) << 2);
            STS64(a0, f2tf(s[ni][0]), f2tf(s[ni][1]));
            STS64(a0 + 2176, f2tf(s[ni][2]), f2tf(s[ni][3]));  // row +8
        }
        __syncwarp();

        // O += P @ V
#pragma unroll
        for (int ki = 0; ki < 8; ki++) {
            uint32_t pf[4];
            ldsm4(pf, PsB + p_lane + ki * 32);
#pragma unroll
            for (int t = 0; t < 4; t++) {
                uint32_t bq[4];
                ldsm4(bq, vsb + kb_lane + t * 4352 + ki * 32);
                mma8(o[2 * t], pf, bq);
                mma8(o[2 * t + 1], pf, bq + 2);
            }
        }
    }

    // epilogue: normalize, tf32-round, write [b][s][e]
    const int b = bh >> 4, h = bh & 15;
    const float i0 = 1.f / l0, i1 = 1.f / l1;
    float* ob = O + ((size_t)b * Sc) * Ec + h * HDc;
    const int row0 = q0 + rb + gr;
#pragma unroll
    for (int ni = 0; ni < 8; ni++) {
        const int d = (ni << 3) + (gc << 1);
        *(float2*)&ob[(size_t)row0 * Ec + d] =
            make_float2(__uint_as_float(f2tf(o[ni][0] * i0)),
                        __uint_as_float(f2tf(o[ni][1] * i0)));
        *(float2*)&ob[(size_t)(row0 + 8) * Ec + d] =
            make_float2(__uint_as_float(f2tf(o[ni][2] * i1)),
                        __uint_as_float(f2tf(o[ni][3] * i1)));
    }
}

// ---------------------------------------------------------------------------
// Inputs: 0 values, 1 keys, 2 queries, 3 mask, 4 Wv, 5 bv, 6 Wk, 7 bk,
//         8 Wq, 9 bq, 10 Wo, 11 bo
// ---------------------------------------------------------------------------
extern "C" void kernel_launch(void* const* d_in, const int* in_sizes, int n_in,
                              void* d_out, int out_size) {
    const float* values = (const float*)d_in[0];
    const float* keys = (const float*)d_in[1];
    const float* queries = (const float*)d_in[2];
    const float* Wv = (const float*)d_in[4];
    const float* bv = (const float*)d_in[5];
    const float* Wk = (const float*)d_in[6];
    const float* bk = (const float*)d_in[7];
    const float* Wq = (const float*)d_in[8];
    const float* bq = (const float*)d_in[9];
    const float* Wo = (const float*)d_in[10];
    const float* bo = (const float*)d_in[11];
    float* out = (float*)d_out;

    float *qb_, *kb_, *vb_, *ab_, *wq_, *wk_, *wv_, *wo_, *qi_, *ki_, *vi_;
    cudaGetSymbolAddress((void**)&qb_, g_q);
    cudaGetSymbolAddress((void**)&kb_, g_k);
    cudaGetSymbolAddress((void**)&vb_, g_v);
    cudaGetSymbolAddress((void**)&ab_, g_attn);
    cudaGetSymbolAddress((void**)&wq_, g_wq);
    cudaGetSymbolAddress((void**)&wk_, g_wk);
    cudaGetSymbolAddress((void**)&wv_, g_wv);
    cudaGetSymbolAddress((void**)&wo_, g_wo);
    cudaGetSymbolAddress((void**)&qi_, g_qin);
    cudaGetSymbolAddress((void**)&ki_, g_kin);
    cudaGetSymbolAddress((void**)&vi_, g_vin);

    const int gemm_smem = 73728;
    const int attn_smem = 104448;
    cudaFuncSetAttribute(gemm_tc<0>, cudaFuncAttributeMaxDynamicSharedMemorySize, gemm_smem);
    cudaFuncSetAttribute(gemm_tc<1>, cudaFuncAttributeMaxDynamicSharedMemorySize, gemm_smem);
    cudaFuncSetAttribute(gemm_tc<2>, cudaFuncAttributeMaxDynamicSharedMemorySize, gemm_smem);
    cudaFuncSetAttribute(gemm_tc<3>, cudaFuncAttributeMaxDynamicSharedMemorySize, gemm_smem);
    cudaFuncSetAttribute(attn_tc, cudaFuncAttributeMaxDynamicSharedMemorySize, attn_smem);

    const int nW4 = Ec * Ec / 4, nI4 = Mrows * Ec / 4;
    conv_tf<<<512, 256>>>((const float4*)Wq, (uint4*)wq_, nW4);
    conv_tf<<<512, 256>>>((const float4*)Wk, (uint4*)wk_, nW4);
    conv_tf<<<512, 256>>>((const float4*)Wv, (uint4*)wv_, nW4);
    conv_tf<<<512, 256>>>((const float4*)Wo, (uint4*)wo_, nW4);
    conv_tf<<<2048, 256>>>((const float4*)queries, (uint4*)qi_, nI4);
    conv_tf<<<2048, 256>>>((const float4*)keys, (uint4*)ki_, nI4);
    conv_tf<<<2048, 256>>>((const float4*)values, (uint4*)vi_, nI4);

    dim3 gg(Mrows / 128, Ec / 128);  // (64, 8)
    gemm_tc<1><<<gg, 256, gemm_smem>>>(qi_, wq_, bq, qb_);
    gemm_tc<2><<<gg, 256, gemm_smem>>>(ki_, wk_, bk, kb_);
    gemm_tc<3><<<gg, 256, gemm_smem>>>(vi_, wv_, bv, vb_);

    dim3 ga(Sc / 128, 4 * Hc);  // (16, 64)
    attn_tc<<<ga, 256, attn_smem>>>(qb_, kb_, vb_, ab_);

    gemm_tc<0><<<gg, 256, gemm_smem>>>(ab_, wo_, bo, out);
}

// round 8
// speedup vs baseline: 4.4361x; 1.0439x over previous
#include <cuda_runtime.h>
#include <cstdint>

#define Sc 2048
#define Ec 1024
#define Hc 16
#define HDc 64
#define Mrows 8192

// Scratch. q/k: [bh][s][d] tf32-bits; v: [bh][d][s] tf32-bits; attn: [b][s][e] tf32-bits
__device__ float g_q[(size_t)Mrows * Ec];
__device__ float g_k[(size_t)Mrows * Ec];
__device__ float g_v[(size_t)Mrows * Ec];
__device__ float g_attn[(size_t)Mrows * Ec];
// tf32 pre-converted weights
__device__ float g_wq[(size_t)Ec * Ec];
__device__ float g_wk[(size_t)Ec * Ec];
__device__ float g_wv[(size_t)Ec * Ec];
__device__ float g_wo[(size_t)Ec * Ec];

__device__ __forceinline__ uint32_t f2tf(float f) {
    uint32_t u;
    asm("cvt.rna.tf32.f32 %0, %1;" : "=r"(u) : "f"(f));
    return u;
}

__device__ __forceinline__ void mma8(float c[4], const uint32_t a[4],
                                     const uint32_t b[2]) {
    asm volatile(
        "mma.sync.aligned.m16n8k8.row.col.f32.tf32.tf32.f32 "
        "{%0,%1,%2,%3}, {%4,%5,%6,%7}, {%8,%9}, {%0,%1,%2,%3};\n"
        : "+f"(c[0]), "+f"(c[1]), "+f"(c[2]), "+f"(c[3])
        : "r"(a[0]), "r"(a[1]), "r"(a[2]), "r"(a[3]), "r"(b[0]), "r"(b[1]));
}

__device__ __forceinline__ void ldsm4(uint32_t r[4], uint32_t a) {
    asm volatile(
        "ldmatrix.sync.aligned.m8n8.x4.shared.b16 {%0,%1,%2,%3}, [%4];"
        : "=r"(r[0]), "=r"(r[1]), "=r"(r[2]), "=r"(r[3])
        : "r"(a));
}

__device__ __forceinline__ void cp16(uint32_t s, const float* g) {
    asm volatile("cp.async.cg.shared.global [%0], [%1], 16;" ::"r"(s), "l"(g)
                 : "memory");
}
#define CP_COMMIT asm volatile("cp.async.commit_group;" ::: "memory")
#define CP_WAIT(n) asm volatile("cp.async.wait_group %0;" ::"n"(n) : "memory")
#define STS64(a, u0, u1) \
    asm volatile("st.shared.v2.b32 [%0], {%1,%2};" ::"r"(a), "r"(u0), "r"(u1))
#define STS128(a, u0, u1, u2, u3)                                      \
    asm volatile("st.shared.v4.b32 [%0], {%1,%2,%3,%4};" ::"r"(a),     \
                 "r"(u0), "r"(u1), "r"(u2), "r"(u3))

// ---------------------------------------------------------------------------
// tf32 pre-convert for the 4 weight matrices in one launch (blockIdx.y picks)
// ---------------------------------------------------------------------------
__global__ void conv_w(const float4* __restrict__ s0, uint4* __restrict__ d0,
                       const float4* __restrict__ s1, uint4* __restrict__ d1,
                       const float4* __restrict__ s2, uint4* __restrict__ d2,
                       const float4* __restrict__ s3, uint4* __restrict__ d3) {
    const float4* src;
    uint4* dst;
    switch (blockIdx.y) {
        case 0: src = s0; dst = d0; break;
        case 1: src = s1; dst = d1; break;
        case 2: src = s2; dst = d2; break;
        default: src = s3; dst = d3; break;
    }
    const int n4 = Ec * Ec / 4;
    int i = blockIdx.x * blockDim.x + threadIdx.x;
    const int stride = gridDim.x * blockDim.x;
    for (; i < n4; i += stride) {
        float4 v = src[i];
        dst[i] = make_uint4(f2tf(v.x), f2tf(v.y), f2tf(v.z), f2tf(v.w));
    }
}

// ---------------------------------------------------------------------------
// GEMM: C[M,1024] = A @ W^T + bias. W always tf32-bits via cp.async.
// CVTA=1: A is raw fp32, converted during LDG->cvt->STS staging (reg prefetch).
// CVTA=0: A already tf32-bits, staged via cp.async.
// CTA 128x128, BK=32, double-buffered, ldmatrix fragments.
// EPI: 0 fp32 out; 1 Q (x0.125, tf32, [bh][s][d]); 2 K (tf32, [bh][s][d]);
//      3 V (tf32, transposed [bh][d][s])
// SMEM per stage: As 128x36 + Ws 128x36 words = 36864 B; 2 stages = 73728 B
// ---------------------------------------------------------------------------
template <int EPI, int CVTA>
__global__ void __launch_bounds__(256, 2)
    gemm_tc(const float* __restrict__ A, const float* __restrict__ W,
            const float* __restrict__ bias, float* __restrict__ C) {
    extern __shared__ uint32_t gsm[];
    const uint32_t smb = (uint32_t)__cvta_generic_to_shared(gsm);

    const int tid = threadIdx.x, lane = tid & 31, warp = tid >> 5;
    const int wm = warp >> 2, wn = warp & 3;  // 2(m) x 4(n)
    const int gr = lane >> 2, gc = lane & 3;
    const int r0 = blockIdx.x << 7, c0 = blockIdx.y << 7;

    const int lm15 = lane & 15;
    const int colA = ((lane >> 4) & 1) << 2;  // A frag k-half
    const int l7 = lane & 7;
    const int l16 = (lane >> 4) & 1;
    const int colB = ((lane >> 3) & 1) << 2;  // B frag k-half

    // ldmatrix lane byte-offsets (within stage)
    const uint32_t a_lane = (((wm << 6) + lm15) * 36 + colA) << 2;
    const uint32_t b_lane = (((wn << 5) + (l16 << 3) + l7) * 36 + colB) << 2;

    // staging coords: 32 rows/pass, 8 lanes x 16B per row (4 passes)
    const int srow = tid >> 3, scol = (tid & 7) << 2;
    const float* Ap = A + (size_t)(r0 + srow) * Ec + scol;
    const float* Wp = W + (size_t)(c0 + srow) * Ec + scol;
    const uint32_t dA = smb + ((srow * 36 + scol) << 2);
    const uint32_t dW = dA + 18432;

    float acc[4][4][4];
#pragma unroll
    for (int mi = 0; mi < 4; mi++)
#pragma unroll
        for (int ni = 0; ni < 4; ni++)
#pragma unroll
            for (int j = 0; j < 4; j++) acc[mi][ni][j] = 0.f;

    // prologue
    float4 pa[4];
#pragma unroll
    for (int p = 0; p < 4; p++) {
        if (CVTA) {
            pa[p] = *(const float4*)(Ap + (size_t)(p << 5) * Ec);
        } else {
            cp16(dA + p * (32 * 36 * 4), Ap + (size_t)(p << 5) * Ec);
        }
        cp16(dW + p * (32 * 36 * 4), Wp + (size_t)(p << 5) * Ec);
    }
    CP_COMMIT;

    for (int c = 0; c < 32; c++) {
        __syncthreads();
        if (CVTA) {
            // store converted A chunk c into its stage
            const uint32_t st_c = (c & 1) * 36864;
#pragma unroll
            for (int p = 0; p < 4; p++) {
                STS128(dA + st_c + p * (32 * 36 * 4), f2tf(pa[p].x),
                       f2tf(pa[p].y), f2tf(pa[p].z), f2tf(pa[p].w));
            }
        }
        if (c + 1 < 32) {
            const uint32_t st = ((c + 1) & 1) * 36864;
            const float* Ap2 = Ap + (c + 1) * 32;
            const float* Wp2 = Wp + (c + 1) * 32;
#pragma unroll
            for (int p = 0; p < 4; p++) {
                if (!CVTA)
                    cp16(dA + st + p * (32 * 36 * 4),
                         Ap2 + (size_t)(p << 5) * Ec);
                cp16(dW + st + p * (32 * 36 * 4), Wp2 + (size_t)(p << 5) * Ec);
            }
            CP_COMMIT;
            if (CVTA) {
#pragma unroll
                for (int p = 0; p < 4; p++)
                    pa[p] = *(const float4*)(Ap2 + (size_t)(p << 5) * Ec);
            }
            CP_WAIT(1);
        } else {
            CP_WAIT(0);
        }
        __syncthreads();

        const uint32_t asb = smb + (c & 1) * 36864;
        const uint32_t wsb = asb + 18432;
#pragma unroll
        for (int ki = 0; ki < 4; ki++) {
            uint32_t af[4][4];
#pragma unroll
            for (int mi = 0; mi < 4; mi++)
                ldsm4(af[mi], asb + a_lane + mi * 2304 + ki * 32);
#pragma unroll
            for (int t = 0; t < 2; t++) {
                uint32_t bq[4];
                ldsm4(bq, wsb + b_lane + t * 2304 + ki * 32);
#pragma unroll
                for (int mi = 0; mi < 4; mi++) {
                    mma8(acc[mi][2 * t], af[mi], bq);
                    mma8(acc[mi][2 * t + 1], af[mi], bq + 2);
                }
            }
        }
    }

    // Epilogue
#pragma unroll
    for (int ni = 0; ni < 4; ni++) {
        const int col = c0 + (wn << 5) + (ni << 3) + (gc << 1);
        const float2 b2 = *(const float2*)&bias[col];
#pragma unroll
        for (int mi = 0; mi < 4; mi++) {
            const int row = r0 + (wm << 6) + (mi << 4) + gr;
            float v00 = acc[mi][ni][0] + b2.x, v01 = acc[mi][ni][1] + b2.y;
            float v10 = acc[mi][ni][2] + b2.x, v11 = acc[mi][ni][3] + b2.y;
            if (EPI == 0) {
                *(float2*)&C[(size_t)row * Ec + col] = make_float2(v00, v01);
                *(float2*)&C[(size_t)(row + 8) * Ec + col] =
                    make_float2(v10, v11);
            } else {
                if (EPI == 1) {
                    v00 *= 0.125f; v01 *= 0.125f; v10 *= 0.125f; v11 *= 0.125f;
                }
                const uint32_t u00 = f2tf(v00), u01 = f2tf(v01);
                const uint32_t u10 = f2tf(v10), u11 = f2tf(v11);
                const int b = row >> 11, s = row & (Sc - 1);
                const int h = col >> 6, d = col & (HDc - 1);
                const int bh = (b << 4) + h;
                if (EPI == 3) {
                    // [bh][d][s]
                    float* base0 = C + (((size_t)(bh << 6) + d) << 11) + s;
                    float* base1 = base0 + Sc;  // d+1
                    base0[0] = __uint_as_float(u00);
                    base0[8] = __uint_as_float(u10);
                    base1[0] = __uint_as_float(u01);
                    base1[8] = __uint_as_float(u11);
                } else {
                    // [bh][s][d]
                    float* base = C + ((size_t)bh << 17) + (s << 6) + d;
                    *(float2*)base = make_float2(__uint_as_float(u00),
                                                 __uint_as_float(u01));
                    *(float2*)(base + (8 << 6)) = make_float2(
                        __uint_as_float(u10), __uint_as_float(u11));
                }
            }
        }
    }
}

// ---------------------------------------------------------------------------
// Flash attention, tf32, ldmatrix + cp.async double-buffered K/V.
// CTA = 128 queries of one (b,h); 8 warps x 16-row strips; K-tile 64.
// Q/K/V already tf32-bits (Q pre-scaled). V in [bh][d][s].
// SMEM bytes: KV stage0 [0,34816), stage1 [34816,69632), Ps/Q [69632,104448).
// ---------------------------------------------------------------------------
__global__ void __launch_bounds__(256, 2)
    attn_tc(const float* __restrict__ Q, const float* __restrict__ K,
            const float* __restrict__ V, float* __restrict__ O) {
    extern __shared__ uint32_t asm_sm[];
    const uint32_t smb = (uint32_t)__cvta_generic_to_shared(asm_sm);
    const uint32_t PsB = smb + 69632;

    const int tid = threadIdx.x, lane = tid & 31, warp = tid >> 5;
    const int gr = lane >> 2, gc = lane & 3;
    const int qi = gridDim.x - 1 - blockIdx.x;  // heavy tiles first
    const int bh = blockIdx.y;
    const int q0 = qi << 7;
    const int rb = warp << 4;

    const int lm15 = lane & 15;
    const int colA = ((lane >> 4) & 1) << 2;
    const int l7 = lane & 7;
    const int l16 = (lane >> 4) & 1;
    const int colB = ((lane >> 3) & 1) << 2;

    const uint32_t p_lane = (((rb + lm15) * 68 + colA) << 2);         // Q/P frags
    const uint32_t kb_lane = ((((l16 << 3) + l7) * 68 + colB) << 2);  // K/V frags

    const float* qb = Q + ((size_t)bh << 17);
    const float* kb = K + ((size_t)bh << 17);
    const float* vb = V + ((size_t)bh << 17);

    // cp.async staging coords: 16 rows/pass x 16 lanes x 16B
    const int srow = tid >> 4, sc4 = (tid & 15) << 2;
    const uint32_t dKV = smb + (((srow * 68) + sc4) << 2);

    // prologue: stage 0 K/V (tile 0)
#pragma unroll
    for (int p = 0; p < 4; p++) {
        const int r = srow + (p << 4);
        cp16(dKV + p * (16 * 68 * 4), kb + (size_t)r * HDc + sc4);
        cp16(dKV + 17408 + p * (16 * 68 * 4), vb + ((size_t)r << 11) + sc4);
    }
    CP_COMMIT;

    // stage Q through the Ps region (disjoint from cp.async targets)
#pragma unroll
    for (int p = 0; p < 8; p++) {
        const int idx = tid + (p << 8);
        const int row = idx >> 4, c4 = (idx & 15) << 2;
        uint4 t = *(const uint4*)(qb + (size_t)(q0 + row) * HDc + c4);
        *(uint4*)((char*)asm_sm + 69632 + ((row * 68 + c4) << 2)) = t;
    }
    __syncthreads();
    uint32_t qf[8][4];
#pragma unroll
    for (int ki = 0; ki < 8; ki++) ldsm4(qf[ki], PsB + p_lane + ki * 32);
    __syncthreads();  // all Q-frag reads done before Ps is reused for P

    float m0 = -1e30f, m1 = -1e30f, l0 = 0.f, l1 = 0.f;
    float o[8][4];
#pragma unroll
    for (int ni = 0; ni < 8; ni++)
#pragma unroll
        for (int j = 0; j < 4; j++) o[ni][j] = 0.f;

    const int ktiles = (qi << 1) + 2;
    for (int kt = 0; kt < ktiles; kt++) {
        __syncthreads();
        if (kt + 1 < ktiles) {
            const int nk0 = (kt + 1) << 6;
            const uint32_t st = ((kt + 1) & 1) * 34816;
#pragma unroll
            for (int p = 0; p < 4; p++) {
                const int r = srow + (p << 4);
                cp16(dKV + st + p * (16 * 68 * 4),
                     kb + (size_t)(nk0 + r) * HDc + sc4);
                cp16(dKV + st + 17408 + p * (16 * 68 * 4),
                     vb + ((size_t)r << 11) + nk0 + sc4);
            }
            CP_COMMIT;
            CP_WAIT(1);
        } else {
            CP_WAIT(0);
        }
        __syncthreads();

        const uint32_t ksb = smb + (kt & 1) * 34816;
        const uint32_t vsb = ksb + 17408;

        // S = Q @ K^T
        float s[8][4];
#pragma unroll
        for (int ni = 0; ni < 8; ni++)
#pragma unroll
            for (int j = 0; j < 4; j++) s[ni][j] = 0.f;
#pragma unroll
        for (int ki = 0; ki < 8; ki++) {
#pragma unroll
            for (int t = 0; t < 4; t++) {
                uint32_t bq[4];
                ldsm4(bq, ksb + kb_lane + t * 4352 + ki * 32);
                mma8(s[2 * t], qf[ki], bq);
                mma8(s[2 * t + 1], qf[ki], bq + 2);
            }
        }

        // causal mask on diagonal-overlapping tiles
        const int k0 = kt << 6;
        if (k0 + 63 > q0) {
            const int row0 = q0 + rb + gr, row1 = row0 + 8;
#pragma unroll
            for (int ni = 0; ni < 8; ni++) {
                const int cg = k0 + (ni << 3) + (gc << 1);
                if (cg > row0) s[ni][0] = -1e30f;
                if (cg + 1 > row0) s[ni][1] = -1e30f;
                if (cg > row1) s[ni][2] = -1e30f;
                if (cg + 1 > row1) s[ni][3] = -1e30f;
            }
        }

        // online softmax
        float mx0 = -1e30f, mx1 = -1e30f;
#pragma unroll
        for (int ni = 0; ni < 8; ni++) {
            mx0 = fmaxf(mx0, fmaxf(s[ni][0], s[ni][1]));
            mx1 = fmaxf(mx1, fmaxf(s[ni][2], s[ni][3]));
        }
        mx0 = fmaxf(mx0, __shfl_xor_sync(0xffffffffu, mx0, 1));
        mx0 = fmaxf(mx0, __shfl_xor_sync(0xffffffffu, mx0, 2));
        mx1 = fmaxf(mx1, __shfl_xor_sync(0xffffffffu, mx1, 1));
        mx1 = fmaxf(mx1, __shfl_xor_sync(0xffffffffu, mx1, 2));

        const float mn0 = fmaxf(m0, mx0), mn1 = fmaxf(m1, mx1);
        const float cor0 = __expf(m0 - mn0), cor1 = __expf(m1 - mn1);
        float sum0 = 0.f, sum1 = 0.f;
#pragma unroll
        for (int ni = 0; ni < 8; ni++) {
            s[ni][0] = __expf(s[ni][0] - mn0);
            s[ni][1] = __expf(s[ni][1] - mn0);
            s[ni][2] = __expf(s[ni][2] - mn1);
            s[ni][3] = __expf(s[ni][3] - mn1);
            sum0 += s[ni][0] + s[ni][1];
            sum1 += s[ni][2] + s[ni][3];
        }
        sum0 += __shfl_xor_sync(0xffffffffu, sum0, 1);
        sum0 += __shfl_xor_sync(0xffffffffu, sum0, 2);
        sum1 += __shfl_xor_sync(0xffffffffu, sum1, 1);
        sum1 += __shfl_xor_sync(0xffffffffu, sum1, 2);

        l0 = l0 * cor0 + sum0;
        l1 = l1 * cor1 + sum1;
        m0 = mn0;
        m1 = mn1;
#pragma unroll
        for (int ni = 0; ni < 8; ni++) {
            o[ni][0] *= cor0;
            o[ni][1] *= cor0;
            o[ni][2] *= cor1;
            o[ni][3] *= cor1;
        }

        // P -> Ps (tf32); rows are warp-private, __syncwarp suffices
#pragma unroll
        for (int ni = 0; ni < 8; ni++) {
            const uint32_t a0 =
                PsB + ((((rb + gr) * 68) + (ni << 3) + (gc << 1)) << 2);
            STS64(a0, f2tf(s[ni][0]), f2tf(s[ni][1]));
            STS64(a0 + 2176, f2tf(s[ni][2]), f2tf(s[ni][3]));  // row +8
        }
        __syncwarp();

        // O += P @ V
#pragma unroll
        for (int ki = 0; ki < 8; ki++) {
            uint32_t pf[4];
            ldsm4(pf, PsB + p_lane + ki * 32);
#pragma unroll
            for (int t = 0; t < 4; t++) {
                uint32_t bq[4];
                ldsm4(bq, vsb + kb_lane + t * 4352 + ki * 32);
                mma8(o[2 * t], pf, bq);
                mma8(o[2 * t + 1], pf, bq + 2);
            }
        }
    }

    // epilogue: normalize, tf32-round, write [b][s][e]
    const int b = bh >> 4, h = bh & 15;
    const float i0 = 1.f / l0, i1 = 1.f / l1;
    float* ob = O + ((size_t)b * Sc) * Ec + h * HDc;
    const int row0 = q0 + rb + gr;
#pragma unroll
    for (int ni = 0; ni < 8; ni++) {
        const int d = (ni << 3) + (gc << 1);
        *(float2*)&ob[(size_t)row0 * Ec + d] =
            make_float2(__uint_as_float(f2tf(o[ni][0] * i0)),
                        __uint_as_float(f2tf(o[ni][1] * i0)));
        *(float2*)&ob[(size_t)(row0 + 8) * Ec + d] =
            make_float2(__uint_as_float(f2tf(o[ni][2] * i1)),
                        __uint_as_float(f2tf(o[ni][3] * i1)));
    }
}

// ---------------------------------------------------------------------------
// Inputs: 0 values, 1 keys, 2 queries, 3 mask, 4 Wv, 5 bv, 6 Wk, 7 bk,
//         8 Wq, 9 bq, 10 Wo, 11 bo
// ---------------------------------------------------------------------------
extern "C" void kernel_launch(void* const* d_in, const int* in_sizes, int n_in,
                              void* d_out, int out_size) {
    const float* values = (const float*)d_in[0];
    const float* keys = (const float*)d_in[1];
    const float* queries = (const float*)d_in[2];
    const float* Wv = (const float*)d_in[4];
    const float* bv = (const float*)d_in[5];
    const float* Wk = (const float*)d_in[6];
    const float* bk = (const float*)d_in[7];
    const float* Wq = (const float*)d_in[8];
    const float* bq = (const float*)d_in[9];
    const float* Wo = (const float*)d_in[10];
    const float* bo = (const float*)d_in[11];
    float* out = (float*)d_out;

    float *qb_, *kb_, *vb_, *ab_, *wq_, *wk_, *wv_, *wo_;
    cudaGetSymbolAddress((void**)&qb_, g_q);
    cudaGetSymbolAddress((void**)&kb_, g_k);
    cudaGetSymbolAddress((void**)&vb_, g_v);
    cudaGetSymbolAddress((void**)&ab_, g_attn);
    cudaGetSymbolAddress((void**)&wq_, g_wq);
    cudaGetSymbolAddress((void**)&wk_, g_wk);
    cudaGetSymbolAddress((void**)&wv_, g_wv);
    cudaGetSymbolAddress((void**)&wo_, g_wo);

    const int gemm_smem = 73728;
    const int attn_smem = 104448;
    cudaFuncSetAttribute(gemm_tc<0, 0>, cudaFuncAttributeMaxDynamicSharedMemorySize, gemm_smem);
    cudaFuncSetAttribute(gemm_tc<1, 1>, cudaFuncAttributeMaxDynamicSharedMemorySize, gemm_smem);
    cudaFuncSetAttribute(gemm_tc<2, 1>, cudaFuncAttributeMaxDynamicSharedMemorySize, gemm_smem);
    cudaFuncSetAttribute(gemm_tc<3, 1>, cudaFuncAttributeMaxDynamicSharedMemorySize, gemm_smem);
    cudaFuncSetAttribute(attn_tc, cudaFuncAttributeMaxDynamicSharedMemorySize, attn_smem);

    // one launch converts all 4 weight matrices
    dim3 gw(256, 4);
    conv_w<<<gw, 256>>>((const float4*)Wq, (uint4*)wq_, (const float4*)Wk,
                        (uint4*)wk_, (const float4*)Wv, (uint4*)wv_,
                        (const float4*)Wo, (uint4*)wo_);

    dim3 gg(Mrows / 128, Ec / 128);  // (64, 8)
    gemm_tc<1, 1><<<gg, 256, gemm_smem>>>(queries, wq_, bq, qb_);
    gemm_tc<2, 1><<<gg, 256, gemm_smem>>>(keys, wk_, bk, kb_);
    gemm_tc<3, 1><<<gg, 256, gemm_smem>>>(values, wv_, bv, vb_);

    dim3 ga(Sc / 128, 4 * Hc);  // (16, 64)
    attn_tc<<<ga, 256, attn_smem>>>(qb_, kb_, vb_, ab_);

    gemm_tc<0, 0><<<gg, 256, gemm_smem>>>(ab_, wo_, bo, out);
}

// round 10
// speedup vs baseline: 4.4395x; 1.0008x over previous
#include <cuda_runtime.h>
#include <cstdint>

#define Sc 2048
#define Ec 1024
#define Hc 16
#define HDc 64
#define Mrows 8192

// Scratch. q/k: [bh][s][d] tf32-bits; v: [bh][d][s] tf32-bits; attn: [b][s][e] tf32-bits
__device__ float g_q[(size_t)Mrows * Ec];
__device__ float g_k[(size_t)Mrows * Ec];
__device__ float g_v[(size_t)Mrows * Ec];
__device__ float g_attn[(size_t)Mrows * Ec];
// tf32 pre-converted weights
__device__ float g_wq[(size_t)Ec * Ec];
__device__ float g_wk[(size_t)Ec * Ec];
__device__ float g_wv[(size_t)Ec * Ec];
__device__ float g_wo[(size_t)Ec * Ec];

__device__ __forceinline__ uint32_t f2tf(float f) {
    uint32_t u;
    asm("cvt.rna.tf32.f32 %0, %1;" : "=r"(u) : "f"(f));
    return u;
}

__device__ __forceinline__ void mma8(float c[4], const uint32_t a[4],
                                     const uint32_t b[2]) {
    asm volatile(
        "mma.sync.aligned.m16n8k8.row.col.f32.tf32.tf32.f32 "
        "{%0,%1,%2,%3}, {%4,%5,%6,%7}, {%8,%9}, {%0,%1,%2,%3};\n"
        : "+f"(c[0]), "+f"(c[1]), "+f"(c[2]), "+f"(c[3])
        : "r"(a[0]), "r"(a[1]), "r"(a[2]), "r"(a[3]), "r"(b[0]), "r"(b[1]));
}

__device__ __forceinline__ void ldsm4(uint32_t r[4], uint32_t a) {
    asm volatile(
        "ldmatrix.sync.aligned.m8n8.x4.shared.b16 {%0,%1,%2,%3}, [%4];"
        : "=r"(r[0]), "=r"(r[1]), "=r"(r[2]), "=r"(r[3])
        : "r"(a));
}

__device__ __forceinline__ void cp16(uint32_t s, const float* g) {
    asm volatile("cp.async.cg.shared.global [%0], [%1], 16;" ::"r"(s), "l"(g)
                 : "memory");
}
#define CP_COMMIT asm volatile("cp.async.commit_group;" ::: "memory")
#define CP_WAIT(n) asm volatile("cp.async.wait_group %0;" ::"n"(n) : "memory")
#define STS64(a, u0, u1) \
    asm volatile("st.shared.v2.b32 [%0], {%1,%2};" ::"r"(a), "r"(u0), "r"(u1))
#define STS128(a, u0, u1, u2, u3)                                  \
    asm volatile("st.shared.v4.b32 [%0], {%1,%2,%3,%4};" ::"r"(a), \
                 "r"(u0), "r"(u1), "r"(u2), "r"(u3))

// ---------------------------------------------------------------------------
// tf32 pre-convert for the 4 weight matrices in one launch (blockIdx.y picks)
// ---------------------------------------------------------------------------
__global__ void conv_w(const float4* __restrict__ s0, uint4* __restrict__ d0,
                       const float4* __restrict__ s1, uint4* __restrict__ d1,
                       const float4* __restrict__ s2, uint4* __restrict__ d2,
                       const float4* __restrict__ s3, uint4* __restrict__ d3) {
    const float4* src;
    uint4* dst;
    switch (blockIdx.y) {
        case 0: src = s0; dst = d0; break;
        case 1: src = s1; dst = d1; break;
        case 2: src = s2; dst = d2; break;
        default: src = s3; dst = d3; break;
    }
    const int n4 = Ec * Ec / 4;
    int i = blockIdx.x * blockDim.x + threadIdx.x;
    const int stride = gridDim.x * blockDim.x;
    for (; i < n4; i += stride) {
        float4 v = src[i];
        dst[i] = make_uint4(f2tf(v.x), f2tf(v.y), f2tf(v.z), f2tf(v.w));
    }
}

// ---------------------------------------------------------------------------
// GEMM: C[M,1024] = A @ W^T + bias. W always tf32-bits via cp.async.
// CVTA=1: A is raw fp32, converted during LDG->cvt->STS staging (prefetch
//         distance: regs hold chunk c+3 at iter c, LDG issued for c+4).
// CVTA=0: A already tf32-bits, staged via cp.async.
// CTA 128x128, BK=32, THREE-stage cp.async ring (CP_WAIT(2): ~2 chunk-times
// of load slack to cover L2 latency), ldmatrix fragments.
// EPI: 0 fp32 out; 1 Q (x0.125, tf32, [bh][s][d]); 2 K (tf32, [bh][s][d]);
//      3 V (tf32, transposed [bh][d][s])
// SMEM per stage: As 128x36 + Ws 128x36 words = 36864 B; 3 stages = 110592 B
// ---------------------------------------------------------------------------
template <int EPI, int CVTA>
__global__ void __launch_bounds__(256, 2)
    gemm_tc(const float* __restrict__ A, const float* __restrict__ W,
            const float* __restrict__ bias, float* __restrict__ C) {
    extern __shared__ uint32_t gsm[];
    const uint32_t smb = (uint32_t)__cvta_generic_to_shared(gsm);

    const int tid = threadIdx.x, lane = tid & 31, warp = tid >> 5;
    const int wm = warp >> 2, wn = warp & 3;  // 2(m) x 4(n)
    const int gr = lane >> 2, gc = lane & 3;
    const int r0 = blockIdx.x << 7, c0 = blockIdx.y << 7;

    const int lm15 = lane & 15;
    const int colA = ((lane >> 4) & 1) << 2;  // A frag k-half
    const int l7 = lane & 7;
    const int l16 = (lane >> 4) & 1;
    const int colB = ((lane >> 3) & 1) << 2;  // B frag k-half

    // ldmatrix lane byte-offsets (within stage)
    const uint32_t a_lane = (((wm << 6) + lm15) * 36 + colA) << 2;
    const uint32_t b_lane = (((wn << 5) + (l16 << 3) + l7) * 36 + colB) << 2;

    // staging coords: 32 rows/pass, 8 lanes x 16B per row (4 passes)
    const int srow = tid >> 3, scol = (tid & 7) << 2;
    const float* Ap = A + (size_t)(r0 + srow) * Ec + scol;
    const float* Wp = W + (size_t)(c0 + srow) * Ec + scol;
    const uint32_t dA0 = smb + ((srow * 36 + scol) << 2);

    float acc[4][4][4];
#pragma unroll
    for (int mi = 0; mi < 4; mi++)
#pragma unroll
        for (int ni = 0; ni < 4; ni++)
#pragma unroll
            for (int j = 0; j < 4; j++) acc[mi][ni][j] = 0.f;

    // prologue: fill stages 0,1,2 with chunks 0,1,2 (one commit group each)
    float4 pa[4];
#pragma unroll
    for (int ch = 0; ch < 3; ch++) {
        const uint32_t st = ch * 36864;
        if (CVTA) {
#pragma unroll
            for (int p = 0; p < 4; p++)
                pa[p] = *(const float4*)(Ap + (size_t)(p << 5) * Ec + (ch << 5));
#pragma unroll
            for (int p = 0; p < 4; p++)
                STS128(dA0 + st + p * (32 * 36 * 4), f2tf(pa[p].x),
                       f2tf(pa[p].y), f2tf(pa[p].z), f2tf(pa[p].w));
        } else {
#pragma unroll
            for (int p = 0; p < 4; p++)
                cp16(dA0 + st + p * (32 * 36 * 4),
                     Ap + (size_t)(p << 5) * Ec + (ch << 5));
        }
#pragma unroll
        for (int p = 0; p < 4; p++)
            cp16(dA0 + st + 18432 + p * (32 * 36 * 4),
                 Wp + (size_t)(p << 5) * Ec + (ch << 5));
        CP_COMMIT;
    }
    if (CVTA) {
        // prefetch chunk 3 into registers
#pragma unroll
        for (int p = 0; p < 4; p++)
            pa[p] = *(const float4*)(Ap + (size_t)(p << 5) * Ec + (3 << 5));
    }

    for (int c = 0; c < 32; c++) {
        if (c < 30) { CP_WAIT(2); } else { CP_WAIT(0); }
        __syncthreads();

        const uint32_t asb = smb + (c % 3) * 36864;
        const uint32_t wsb = asb + 18432;
#pragma unroll
        for (int ki = 0; ki < 4; ki++) {
            uint32_t af[4][4];
#pragma unroll
            for (int mi = 0; mi < 4; mi++)
                ldsm4(af[mi], asb + a_lane + mi * 2304 + ki * 32);
#pragma unroll
            for (int t = 0; t < 2; t++) {
                uint32_t bq[4];
                ldsm4(bq, wsb + b_lane + t * 2304 + ki * 32);
#pragma unroll
                for (int mi = 0; mi < 4; mi++) {
                    mma8(acc[mi][2 * t], af[mi], bq);
                    mma8(acc[mi][2 * t + 1], af[mi], bq + 2);
                }
            }
        }
        __syncthreads();  // all warps done reading stage c%3

        if (c + 3 < 32) {
            const uint32_t st = (c % 3) * 36864;  // == (c+3)%3 slot
            const int nch = c + 3;
            if (CVTA) {
                // pa holds chunk c+3
#pragma unroll
                for (int p = 0; p < 4; p++)
                    STS128(dA0 + st + p * (32 * 36 * 4), f2tf(pa[p].x),
                           f2tf(pa[p].y), f2tf(pa[p].z), f2tf(pa[p].w));
            } else {
#pragma unroll
                for (int p = 0; p < 4; p++)
                    cp16(dA0 + st + p * (32 * 36 * 4),
                         Ap + (size_t)(p << 5) * Ec + (nch << 5));
            }
#pragma unroll
            for (int p = 0; p < 4; p++)
                cp16(dA0 + st + 18432 + p * (32 * 36 * 4),
                     Wp + (size_t)(p << 5) * Ec + (nch << 5));
            CP_COMMIT;
            if (CVTA && c + 4 < 32) {
#pragma unroll
                for (int p = 0; p < 4; p++)
                    pa[p] = *(const float4*)(Ap + (size_t)(p << 5) * Ec +
                                             ((c + 4) << 5));
            }
        }
    }

    // Epilogue
#pragma unroll
    for (int ni = 0; ni < 4; ni++) {
        const int col = c0 + (wn << 5) + (ni << 3) + (gc << 1);
        const float2 b2 = *(const float2*)&bias[col];
#pragma unroll
        for (int mi = 0; mi < 4; mi++) {
            const int row = r0 + (wm << 6) + (mi << 4) + gr;
            float v00 = acc[mi][ni][0] + b2.x, v01 = acc[mi][ni][1] + b2.y;
            float v10 = acc[mi][ni][2] + b2.x, v11 = acc[mi][ni][3] + b2.y;
            if (EPI == 0) {
                *(float2*)&C[(size_t)row * Ec + col] = make_float2(v00, v01);
                *(float2*)&C[(size_t)(row + 8) * Ec + col] =
                    make_float2(v10, v11);
            } else {
                if (EPI == 1) {
                    v00 *= 0.125f; v01 *= 0.125f; v10 *= 0.125f; v11 *= 0.125f;
                }
                const uint32_t u00 = f2tf(v00), u01 = f2tf(v01);
                const uint32_t u10 = f2tf(v10), u11 = f2tf(v11);
                const int b = row >> 11, s = row & (Sc - 1);
                const int h = col >> 6, d = col & (HDc - 1);
                const int bh = (b << 4) + h;
                if (EPI == 3) {
                    // [bh][d][s]
                    float* base0 = C + (((size_t)(bh << 6) + d) << 11) + s;
                    float* base1 = base0 + Sc;  // d+1
                    base0[0] = __uint_as_float(u00);
                    base0[8] = __uint_as_float(u10);
                    base1[0] = __uint_as_float(u01);
                    base1[8] = __uint_as_float(u11);
                } else {
                    // [bh][s][d]
                    float* base = C + ((size_t)bh << 17) + (s << 6) + d;
                    *(float2*)base = make_float2(__uint_as_float(u00),
                                                 __uint_as_float(u01));
                    *(float2*)(base + (8 << 6)) = make_float2(
                        __uint_as_float(u10), __uint_as_float(u11));
                }
            }
        }
    }
}

// ---------------------------------------------------------------------------
// Flash attention (byte-identical to R8): tf32 mma.sync + ldmatrix + cp.async.
// CTA = 128 queries of one (b,h); 8 warps x 16-row strips; K-tile 64.
// SMEM bytes: KV stage0 [0,34816), stage1 [34816,69632), Ps/Q [69632,104448).
// ---------------------------------------------------------------------------
__global__ void __launch_bounds__(256, 2)
    attn_tc(const float* __restrict__ Q, const float* __restrict__ K,
            const float* __restrict__ V, float* __restrict__ O) {
    extern __shared__ uint32_t asm_sm[];
    const uint32_t smb = (uint32_t)__cvta_generic_to_shared(asm_sm);
    const uint32_t PsB = smb + 69632;

    const int tid = threadIdx.x, lane = tid & 31, warp = tid >> 5;
    const int gr = lane >> 2, gc = lane & 3;
    const int qi = gridDim.x - 1 - blockIdx.x;
    const int bh = blockIdx.y;
    const int q0 = qi << 7;
    const int rb = warp << 4;

    const int lm15 = lane & 15;
    const int colA = ((lane >> 4) & 1) << 2;
    const int l7 = lane & 7;
    const int l16 = (lane >> 4) & 1;
    const int colB = ((lane >> 3) & 1) << 2;

    const uint32_t p_lane = (((rb + lm15) * 68 + colA) << 2);
    const uint32_t kb_lane = ((((l16 << 3) + l7) * 68 + colB) << 2);

    const float* qb = Q + ((size_t)bh << 17);
    const float* kb = K + ((size_t)bh << 17);
    const float* vb = V + ((size_t)bh << 17);

    const int srow = tid >> 4, sc4 = (tid & 15) << 2;
    const uint32_t dKV = smb + (((srow * 68) + sc4) << 2);

#pragma unroll
    for (int p = 0; p < 4; p++) {
        const int r = srow + (p << 4);
        cp16(dKV + p * (16 * 68 * 4), kb + (size_t)r * HDc + sc4);
        cp16(dKV + 17408 + p * (16 * 68 * 4), vb + ((size_t)r << 11) + sc4);
    }
    CP_COMMIT;

#pragma unroll
    for (int p = 0; p < 8; p++) {
        const int idx = tid + (p << 8);
        const int row = idx >> 4, c4 = (idx & 15) << 2;
        uint4 t = *(const uint4*)(qb + (size_t)(q0 + row) * HDc + c4);
        *(uint4*)((char*)asm_sm + 69632 + ((row * 68 + c4) << 2)) = t;
    }
    __syncthreads();
    uint32_t qf[8][4];
#pragma unroll
    for (int ki = 0; ki < 8; ki++) ldsm4(qf[ki], PsB + p_lane + ki * 32);
    __syncthreads();

    float m0 = -1e30f, m1 = -1e30f, l0 = 0.f, l1 = 0.f;
    float o[8][4];
#pragma unroll
    for (int ni = 0; ni < 8; ni++)
#pragma unroll
        for (int j = 0; j < 4; j++) o[ni][j] = 0.f;

    const int ktiles = (qi << 1) + 2;
    for (int kt = 0; kt < ktiles; kt++) {
        __syncthreads();
        if (kt + 1 < ktiles) {
            const int nk0 = (kt + 1) << 6;
            const uint32_t st = ((kt + 1) & 1) * 34816;
#pragma unroll
            for (int p = 0; p < 4; p++) {
                const int r = srow + (p << 4);
                cp16(dKV + st + p * (16 * 68 * 4),
                     kb + (size_t)(nk0 + r) * HDc + sc4);
                cp16(dKV + st + 17408 + p * (16 * 68 * 4),
                     vb + ((size_t)r << 11) + nk0 + sc4);
            }
            CP_COMMIT;
            CP_WAIT(1);
        } else {
            CP_WAIT(0);
        }
        __syncthreads();

        const uint32_t ksb = smb + (kt & 1) * 34816;
        const uint32_t vsb = ksb + 17408;

        float s[8][4];
#pragma unroll
        for (int ni = 0; ni < 8; ni++)
#pragma unroll
            for (int j = 0; j < 4; j++) s[ni][j] = 0.f;
#pragma unroll
        for (int ki = 0; ki < 8; ki++) {
#pragma unroll
            for (int t = 0; t < 4; t++) {
                uint32_t bq[4];
                ldsm4(bq, ksb + kb_lane + t * 4352 + ki * 32);
                mma8(s[2 * t], qf[ki], bq);
                mma8(s[2 * t + 1], qf[ki], bq + 2);
            }
        }

        const int k0 = kt << 6;
        if (k0 + 63 > q0) {
            const int row0 = q0 + rb + gr, row1 = row0 + 8;
#pragma unroll
            for (int ni = 0; ni < 8; ni++) {
                const int cg = k0 + (ni << 3) + (gc << 1);
                if (cg > row0) s[ni][0] = -1e30f;
                if (cg + 1 > row0) s[ni][1] = -1e30f;
                if (cg > row1) s[ni][2] = -1e30f;
                if (cg + 1 > row1) s[ni][3] = -1e30f;
            }
        }

        float mx0 = -1e30f, mx1 = -1e30f;
#pragma unroll
        for (int ni = 0; ni < 8; ni++) {
            mx0 = fmaxf(mx0, fmaxf(s[ni][0], s[ni][1]));
            mx1 = fmaxf(mx1, fmaxf(s[ni][2], s[ni][3]));
        }
        mx0 = fmaxf(mx0, __shfl_xor_sync(0xffffffffu, mx0, 1));
        mx0 = fmaxf(mx0, __shfl_xor_sync(0xffffffffu, mx0, 2));
        mx1 = fmaxf(mx1, __shfl_xor_sync(0xffffffffu, mx1, 1));
        mx1 = fmaxf(mx1, __shfl_xor_sync(0xffffffffu, mx1, 2));

        const float mn0 = fmaxf(m0, mx0), mn1 = fmaxf(m1, mx1);
        const float cor0 = __expf(m0 - mn0), cor1 = __expf(m1 - mn1);
        float sum0 = 0.f, sum1 = 0.f;
#pragma unroll
        for (int ni = 0; ni < 8; ni++) {
            s[ni][0] = __expf(s[ni][0] - mn0);
            s[ni][1] = __expf(s[ni][1] - mn0);
            s[ni][2] = __expf(s[ni][2] - mn1);
            s[ni][3] = __expf(s[ni][3] - mn1);
            sum0 += s[ni][0] + s[ni][1];
            sum1 += s[ni][2] + s[ni][3];
        }
        sum0 += __shfl_xor_sync(0xffffffffu, sum0, 1);
        sum0 += __shfl_xor_sync(0xffffffffu, sum0, 2);
        sum1 += __shfl_xor_sync(0xffffffffu, sum1, 1);
        sum1 += __shfl_xor_sync(0xffffffffu, sum1, 2);

        l0 = l0 * cor0 + sum0;
        l1 = l1 * cor1 + sum1;
        m0 = mn0;
        m1 = mn1;
#pragma unroll
        for (int ni = 0; ni < 8; ni++) {
            o[ni][0] *= cor0;
            o[ni][1] *= cor0;
            o[ni][2] *= cor1;
            o[ni][3] *= cor1;
        }

#pragma unroll
        for (int ni = 0; ni < 8; ni++) {
            const uint32_t a0 =
                PsB + ((((rb + gr) * 68) + (ni << 3) + (gc << 1)) << 2);
            STS64(a0, f2tf(s[ni][0]), f2tf(s[ni][1]));
            STS64(a0 + 2176, f2tf(s[ni][2]), f2tf(s[ni][3]));
        }
        __syncwarp();

#pragma unroll
        for (int ki = 0; ki < 8; ki++) {
            uint32_t pf[4];
            ldsm4(pf, PsB + p_lane + ki * 32);
#pragma unroll
            for (int t = 0; t < 4; t++) {
                uint32_t bq[4];
                ldsm4(bq, vsb + kb_lane + t * 4352 + ki * 32);
                mma8(o[2 * t], pf, bq);
                mma8(o[2 * t + 1], pf, bq + 2);
            }
        }
    }

    const int b = bh >> 4, h = bh & 15;
    const float i0 = 1.f / l0, i1 = 1.f / l1;
    float* ob = O + ((size_t)b * Sc) * Ec + h * HDc;
    const int row0 = q0 + rb + gr;
#pragma unroll
    for (int ni = 0; ni < 8; ni++) {
        const int d = (ni << 3) + (gc << 1);
        *(float2*)&ob[(size_t)row0 * Ec + d] =
            make_float2(__uint_as_float(f2tf(o[ni][0] * i0)),
                        __uint_as_float(f2tf(o[ni][1] * i0)));
        *(float2*)&ob[(size_t)(row0 + 8) * Ec + d] =
            make_float2(__uint_as_float(f2tf(o[ni][2] * i1)),
                        __uint_as_float(f2tf(o[ni][3] * i1)));
    }
}

// ---------------------------------------------------------------------------
// Inputs: 0 values, 1 keys, 2 queries, 3 mask, 4 Wv, 5 bv, 6 Wk, 7 bk,
//         8 Wq, 9 bq, 10 Wo, 11 bo
// ---------------------------------------------------------------------------
extern "C" void kernel_launch(void* const* d_in, const int* in_sizes, int n_in,
                              void* d_out, int out_size) {
    const float* values = (const float*)d_in[0];
    const float* keys = (const float*)d_in[1];
    const float* queries = (const float*)d_in[2];
    const float* Wv = (const float*)d_in[4];
    const float* bv = (const float*)d_in[5];
    const float* Wk = (const float*)d_in[6];
    const float* bk = (const float*)d_in[7];
    const float* Wq = (const float*)d_in[8];
    const float* bq = (const float*)d_in[9];
    const float* Wo = (const float*)d_in[10];
    const float* bo = (const float*)d_in[11];
    float* out = (float*)d_out;

    float *qb_, *kb_, *vb_, *ab_, *wq_, *wk_, *wv_, *wo_;
    cudaGetSymbolAddress((void**)&qb_, g_q);
    cudaGetSymbolAddress((void**)&kb_, g_k);
    cudaGetSymbolAddress((void**)&vb_, g_v);
    cudaGetSymbolAddress((void**)&ab_, g_attn);
    cudaGetSymbolAddress((void**)&wq_, g_wq);
    cudaGetSymbolAddress((void**)&wk_, g_wk);
    cudaGetSymbolAddress((void**)&wv_, g_wv);
    cudaGetSymbolAddress((void**)&wo_, g_wo);

    const int gemm_smem = 110592;  // 3 stages x 36864
    const int attn_smem = 104448;
    cudaFuncSetAttribute(gemm_tc<0, 0>, cudaFuncAttributeMaxDynamicSharedMemorySize, gemm_smem);
    cudaFuncSetAttribute(gemm_tc<1, 1>, cudaFuncAttributeMaxDynamicSharedMemorySize, gemm_smem);
    cudaFuncSetAttribute(gemm_tc<2, 1>, cudaFuncAttributeMaxDynamicSharedMemorySize, gemm_smem);
    cudaFuncSetAttribute(gemm_tc<3, 1>, cudaFuncAttributeMaxDynamicSharedMemorySize, gemm_smem);
    cudaFuncSetAttribute(attn_tc, cudaFuncAttributeMaxDynamicSharedMemorySize, attn_smem);

    // one launch converts all 4 weight matrices
    dim3 gw(256, 4);
    conv_w<<<gw, 256>>>((const float4*)Wq, (uint4*)wq_, (const float4*)Wk,
                        (uint4*)wk_, (const float4*)Wv, (uint4*)wv_,
                        (const float4*)Wo, (uint4*)wo_);

    dim3 gg(Mrows / 128, Ec / 128);  // (64, 8)
    gemm_tc<1, 1><<<gg, 256, gemm_smem>>>(queries, wq_, bq, qb_);
    gemm_tc<2, 1><<<gg, 256, gemm_smem>>>(keys, wk_, bk, kb_);
    gemm_tc<3, 1><<<gg, 256, gemm_smem>>>(values, wv_, bv, vb_);

    dim3 ga(Sc / 128, 4 * Hc);  // (16, 64)
    attn_tc<<<ga, 256, attn_smem>>>(qb_, kb_, vb_, ab_);

    gemm_tc<0, 0><<<gg, 256, gemm_smem>>>(ab_, wo_, bo, out);
}